// round 5
// baseline (speedup 1.0000x reference)
#include <cuda_runtime.h>
#include <cuda_bf16.h>
#include <cstdint>

// Problem constants
#define BATCH 4
#define SEQL 1024
#define HIDDEN 1024
#define QKV_COLS 4096   // 2048 q + 1024 k + 1024 v
#define ATTN_COLS 2048  // 32*64
#define ROWS 4096       // BATCH*SEQL

// ---------------------------------------------------------------------------
// Scratch (__device__ globals; allocation-free rule)
// ---------------------------------------------------------------------------
__device__ float g_qkv[(size_t)ROWS * QKV_COLS];    // fp32 (V region only used)
__device__ __nv_bfloat16 g_Ahi[(size_t)ROWS * HIDDEN];
__device__ __nv_bfloat16 g_Alo[(size_t)ROWS * HIDDEN];
__device__ __nv_bfloat16 g_Wqkv_hi[(size_t)QKV_COLS * HIDDEN];  // [N,K]
__device__ __nv_bfloat16 g_Wqkv_lo[(size_t)QKV_COLS * HIDDEN];
__device__ __nv_bfloat16 g_At2hi[(size_t)ROWS * ATTN_COLS];     // attn out split
__device__ __nv_bfloat16 g_At2lo[(size_t)ROWS * ATTN_COLS];
__device__ __nv_bfloat16 g_Wout_hi[(size_t)HIDDEN * ATTN_COLS]; // [N,K]
__device__ __nv_bfloat16 g_Wout_lo[(size_t)HIDDEN * ATTN_COLS];
// attention operand splits
__device__ __nv_bfloat16 g_Qhi[(size_t)BATCH * 32 * SEQL * 64];   // [b,h,s,d]
__device__ __nv_bfloat16 g_Qlo[(size_t)BATCH * 32 * SEQL * 64];
__device__ __nv_bfloat16 g_Khi[(size_t)BATCH * 16 * SEQL * 64];   // [b,kvh,s,d]
__device__ __nv_bfloat16 g_Klo[(size_t)BATCH * 16 * SEQL * 64];
__device__ __nv_bfloat16 g_Vthi[(size_t)BATCH * 16 * 64 * SEQL];  // [b,kvh,d,s]
__device__ __nv_bfloat16 g_Vtlo[(size_t)BATCH * 16 * 64 * SEQL];

// ---------------------------------------------------------------------------
// PTX helpers (sm_80+ only — NO tcgen05; harness targets compute_103)
// ---------------------------------------------------------------------------
__device__ __forceinline__ uint32_t smem_u32(const void* p) {
    uint32_t a;
    asm("{ .reg .u64 t; cvta.to.shared.u64 t, %1; cvt.u32.u64 %0, t; }" : "=r"(a) : "l"(p));
    return a;
}
__device__ __forceinline__ void cp16(uint32_t dst, const void* src) {
    asm volatile("cp.async.cg.shared.global [%0], [%1], 16;" :: "r"(dst), "l"(src));
}
#define CP_COMMIT() asm volatile("cp.async.commit_group;" ::: "memory")
#define CP_WAIT1()  asm volatile("cp.async.wait_group 1;" ::: "memory")

__device__ __forceinline__ void ldm_x4(uint32_t* r, uint32_t addr) {
    asm volatile("ldmatrix.sync.aligned.m8n8.x4.shared.b16 {%0,%1,%2,%3}, [%4];"
                 : "=r"(r[0]), "=r"(r[1]), "=r"(r[2]), "=r"(r[3]) : "r"(addr));
}
__device__ __forceinline__ void mma_bf16(float* d, const uint32_t* a, const uint32_t* b) {
    asm volatile(
        "mma.sync.aligned.m16n8k16.row.col.f32.bf16.bf16.f32 "
        "{%0,%1,%2,%3}, {%4,%5,%6,%7}, {%8,%9}, {%0,%1,%2,%3};"
        : "+f"(d[0]), "+f"(d[1]), "+f"(d[2]), "+f"(d[3])
        : "r"(a[0]), "r"(a[1]), "r"(a[2]), "r"(a[3]), "r"(b[0]), "r"(b[1]));
}
__device__ __forceinline__ uint32_t cvt_bf16x2(float f0, float f1) {
    uint32_t r;
    asm("cvt.rn.bf16x2.f32 %0, %1, %2;" : "=r"(r) : "f"(f1), "f"(f0));
    return r;
}
__device__ __forceinline__ void split_pair(float f0, float f1, uint32_t& hi, uint32_t& lo) {
    hi = cvt_bf16x2(f0, f1);
    float r0 = __uint_as_float(hi << 16);
    float r1 = __uint_as_float(hi & 0xffff0000u);
    lo = cvt_bf16x2(f0 - r0, f1 - r1);
}

// ---------------------------------------------------------------------------
// HMMA GEMM: C = A[M,K] * B[N,K]^T, bf16 3-product split, ldmatrix fragments.
// mode 0: plain fp32 C store. mode 1: QKV fused epilogue (Q/K split, V fp32).
// ---------------------------------------------------------------------------
#define RSTRIDE 40
#define RS2 (RSTRIDE * 2)
#define SLAB (128 * RS2)
#define STAGE (4 * SLAB)
#define GSM_TOTAL (2 * STAGE)

__global__ __launch_bounds__(256)
void gemm_tc_kernel(const __nv_bfloat16* __restrict__ Ahi,
                    const __nv_bfloat16* __restrict__ Alo,
                    const __nv_bfloat16* __restrict__ Bhi,
                    const __nv_bfloat16* __restrict__ Blo,
                    float* __restrict__ C, int Ndim, int Kdim, int mode) {
    extern __shared__ __align__(256) char smem[];
    const uint32_t sbase = smem_u32(smem);
    const int tid = threadIdx.x;
    const int lane = tid & 31;
    const int warp = tid >> 5;
    const int wm = warp & 1;
    const int wn = warp >> 1;
    const int brow = blockIdx.y * 128;
    const int bcol = blockIdx.x * 128;

    const __nv_bfloat16* mats[4] = {Ahi, Alo, Bhi, Blo};
    const int KT = Kdim >> 5;

    auto load_stage = [&](int t) {
        const int s = t & 1;
        const int k0 = t << 5;
        const uint32_t stg = sbase + s * STAGE;
#pragma unroll
        for (int m = 0; m < 4; m++) {
            const int rowbase = (m < 2) ? brow : bcol;
            const __nv_bfloat16* base = mats[m];
#pragma unroll
            for (int u = 0; u < 2; u++) {
                int idx = tid + u * 256;
                int row = idx >> 2;
                int seg = idx & 3;
                const __nv_bfloat16* src =
                    base + (size_t)(rowbase + row) * Kdim + k0 + seg * 8;
                uint32_t dst = stg + m * SLAB + row * RS2 + seg * 16;
                cp16(dst, src);
            }
        }
        CP_COMMIT();
    };

    float acc[4][4][4];
#pragma unroll
    for (int i = 0; i < 4; i++)
#pragma unroll
        for (int j = 0; j < 4; j++)
#pragma unroll
            for (int r = 0; r < 4; r++) acc[i][j][r] = 0.f;

    load_stage(0);
    if (KT > 1) load_stage(1); else CP_COMMIT();

    const int r0 = lane >> 2;
    const int cpair = (lane & 3) * 2;
    const int lrow = lane & 15;
    const int lkoff = (lane >> 4) * 16;

    for (int t = 0; t < KT; t++) {
        CP_WAIT1();
        __syncthreads();
        const uint32_t stg = sbase + (t & 1) * STAGE;
        const uint32_t aHi = stg + (wm * 64) * RS2;
        const uint32_t bHi = stg + 2 * SLAB + (wn * 32) * RS2;

#pragma unroll
        for (int ks = 0; ks < 2; ks++) {
            const uint32_t colb = ks * 32;
            uint32_t ahi[4][4], alo[4][4], bhi[4][2], blo[4][2];
#pragma unroll
            for (int mi = 0; mi < 4; mi++) {
                uint32_t ad = aHi + (mi * 16 + lrow) * RS2 + colb + lkoff;
                ldm_x4(ahi[mi], ad);
                ldm_x4(alo[mi], ad + SLAB);
            }
#pragma unroll
            for (int nj2 = 0; nj2 < 2; nj2++) {
                uint32_t tt[4];
                uint32_t bd = bHi + (nj2 * 16 + lrow) * RS2 + colb + lkoff;
                ldm_x4(tt, bd);
                bhi[2 * nj2][0] = tt[0]; bhi[2 * nj2][1] = tt[2];
                bhi[2 * nj2 + 1][0] = tt[1]; bhi[2 * nj2 + 1][1] = tt[3];
                ldm_x4(tt, bd + SLAB);
                blo[2 * nj2][0] = tt[0]; blo[2 * nj2][1] = tt[2];
                blo[2 * nj2 + 1][0] = tt[1]; blo[2 * nj2 + 1][1] = tt[3];
            }
#pragma unroll
            for (int mi = 0; mi < 4; mi++)
#pragma unroll
                for (int nj = 0; nj < 4; nj++) {
                    mma_bf16(acc[mi][nj], ahi[mi], bhi[nj]);
                    mma_bf16(acc[mi][nj], ahi[mi], blo[nj]);
                    mma_bf16(acc[mi][nj], alo[mi], bhi[nj]);
                }
        }
        __syncthreads();
        if (t + 2 < KT) load_stage(t + 2); else CP_COMMIT();
    }

    // ---- Epilogue ----
    if (mode == 0 || bcol >= 3072) {
        // plain fp32 store (out-proj, or V region of qkv)
#pragma unroll
        for (int mi = 0; mi < 4; mi++) {
            int row = brow + wm * 64 + mi * 16 + r0;
#pragma unroll
            for (int nj = 0; nj < 4; nj++) {
                int col = bcol + wn * 32 + nj * 8 + cpair;
                *(float2*)(C + (size_t)row * Ndim + col) =
                    make_float2(acc[mi][nj][0], acc[mi][nj][1]);
                *(float2*)(C + (size_t)(row + 8) * Ndim + col) =
                    make_float2(acc[mi][nj][2], acc[mi][nj][3]);
            }
        }
    } else {
        // fused Q/K hi-lo split store
        const int b = brow >> 10;
        const bool isQ = (bcol < 2048);
        __nv_bfloat16* dhi = isQ ? g_Qhi : g_Khi;
        __nv_bfloat16* dlo = isQ ? g_Qlo : g_Klo;
        const int hbase = isQ ? (b * 32) : (b * 16);
        const int cadj = isQ ? 0 : 2048;
#pragma unroll
        for (int mi = 0; mi < 4; mi++) {
            int row = brow + wm * 64 + mi * 16 + r0;
            int s = row & 1023;
#pragma unroll
            for (int nj = 0; nj < 4; nj++) {
                int col = bcol - cadj + wn * 32 + nj * 8 + cpair;
                int hh = col >> 6, d = col & 63;
                size_t o0 = ((size_t)(hbase + hh) * 1024 + s) * 64 + d;
                size_t o1 = o0 + (size_t)8 * 64;
                uint32_t ph, pl;
                split_pair(acc[mi][nj][0], acc[mi][nj][1], ph, pl);
                *(uint32_t*)&dhi[o0] = ph;
                *(uint32_t*)&dlo[o0] = pl;
                split_pair(acc[mi][nj][2], acc[mi][nj][3], ph, pl);
                *(uint32_t*)&dhi[o1] = ph;
                *(uint32_t*)&dlo[o1] = pl;
            }
        }
    }
}

// ---------------------------------------------------------------------------
// fp32 -> bf16 hi/lo elementwise split (GEMM A operand)
// ---------------------------------------------------------------------------
__global__ __launch_bounds__(256) void split_kernel(const float* __restrict__ x,
                                                    __nv_bfloat16* __restrict__ hi,
                                                    __nv_bfloat16* __restrict__ lo,
                                                    int n4) {
    int i = blockIdx.x * blockDim.x + threadIdx.x;
    if (i >= n4) return;
    float4 v = ((const float4*)x)[i];
    uint32_t h0, l0, h1, l1;
    split_pair(v.x, v.y, h0, l0);
    split_pair(v.z, v.w, h1, l1);
    ((uint2*)hi)[i] = make_uint2(h0, h1);
    ((uint2*)lo)[i] = make_uint2(l0, l1);
}

// ---------------------------------------------------------------------------
// W[K,N] fp32 -> Wt[N,K] bf16 hi/lo (tiled transpose + split)
// ---------------------------------------------------------------------------
__global__ __launch_bounds__(256) void transpose_split_kernel(
    const float* __restrict__ W, __nv_bfloat16* __restrict__ hi,
    __nv_bfloat16* __restrict__ lo, int K, int N) {
    __shared__ float t[32][33];
    int k0 = blockIdx.y * 32, n0 = blockIdx.x * 32;
    int tx = threadIdx.x, ty = threadIdx.y;  // (32, 8)
#pragma unroll
    for (int j = 0; j < 4; j++)
        t[ty + j * 8][tx] = W[(size_t)(k0 + ty + j * 8) * N + n0 + tx];
    __syncthreads();
#pragma unroll
    for (int j = 0; j < 4; j++) {
        float v = t[tx][ty + j * 8];
        __nv_bfloat16 h = __float2bfloat16(v);
        __nv_bfloat16 l = __float2bfloat16(v - __bfloat162float(h));
        size_t o = (size_t)(n0 + ty + j * 8) * K + k0 + tx;
        hi[o] = h;
        lo[o] = l;
    }
}

// ---------------------------------------------------------------------------
// Prep: V fp32 [b,s,kvh,d] -> Vt hi/lo [b,kvh,d,s]
// ---------------------------------------------------------------------------
__global__ __launch_bounds__(256) void prep_vt_kernel() {
    __shared__ float tile[64][65];
    int s0 = blockIdx.x * 64;
    int bk = blockIdx.y;               // b*16 + kvh
    int b = bk >> 4, kvh = bk & 15;
    int tid = threadIdx.x;
#pragma unroll
    for (int u = 0; u < 4; u++) {
        int lin = tid + u * 256;
        int row = lin >> 4, c4 = lin & 15;
        float4 v = *(const float4*)&g_qkv[((size_t)(b * 1024 + s0 + row)) * 4096 +
                                          3072 + kvh * 64 + c4 * 4];
        tile[row][c4 * 4 + 0] = v.x;
        tile[row][c4 * 4 + 1] = v.y;
        tile[row][c4 * 4 + 2] = v.z;
        tile[row][c4 * 4 + 3] = v.w;
    }
    __syncthreads();
#pragma unroll
    for (int u = 0; u < 4; u++) {
        int lin = tid + u * 256;
        int d = lin >> 4, c4 = lin & 15;
        float f0 = tile[c4 * 4 + 0][d], f1 = tile[c4 * 4 + 1][d];
        float f2 = tile[c4 * 4 + 2][d], f3 = tile[c4 * 4 + 3][d];
        uint32_t h0, l0, h1, l1;
        split_pair(f0, f1, h0, l0);
        split_pair(f2, f3, h1, l1);
        size_t o = ((size_t)bk * 64 + d) * 1024 + s0 + c4 * 4;
        *(uint2*)&g_Vthi[o] = make_uint2(h0, h1);
        *(uint2*)&g_Vtlo[o] = make_uint2(l0, l1);
    }
}

// ---------------------------------------------------------------------------
// Tensor-core flash attention, bf16 hi/lo 3-product split, ldmatrix fragments.
// ---------------------------------------------------------------------------
#define AP 144                    // smem pitch bytes
#define AKV0 (2 * 128 * AP)       // 36864
#define AKV_STAGE (4 * 64 * AP)   // 36864
#define ATT_SMEM (AKV0 + 2 * AKV_STAGE)

__global__ __launch_bounds__(256) void attn_tc_kernel() {
    extern __shared__ __align__(256) char smem[];
    const uint32_t sbase = smem_u32(smem);
    const int tid = threadIdx.x;
    const int lane = tid & 31;
    const int warp = tid >> 5;
    const int bh = blockIdx.x;
    const int b = bh >> 5;
    const int h = bh & 31;
    const int kvh = h >> 1;
    const int qblk = (int)gridDim.y - 1 - (int)blockIdx.y;
    const int q0 = qblk * 128;
    const int wrow = warp * 16;
    const float slope = exp2f(-0.25f * (float)(h + 1));
    const float NINF = -__int_as_float(0x7f800000);

    const __nv_bfloat16* Qhi_g = g_Qhi + ((size_t)(b * 32 + h) * 1024 + q0) * 64;
    const __nv_bfloat16* Qlo_g = g_Qlo + ((size_t)(b * 32 + h) * 1024 + q0) * 64;
    const __nv_bfloat16* Khi_g = g_Khi + (size_t)(b * 16 + kvh) * 1024 * 64;
    const __nv_bfloat16* Klo_g = g_Klo + (size_t)(b * 16 + kvh) * 1024 * 64;
    const __nv_bfloat16* Vthi_g = g_Vthi + (size_t)(b * 16 + kvh) * 64 * 1024;
    const __nv_bfloat16* Vtlo_g = g_Vtlo + (size_t)(b * 16 + kvh) * 64 * 1024;

#pragma unroll
    for (int u = 0; u < 8; u++) {
        int idx = tid + u * 256;
        int slab = idx >> 10;
        int rem = idx & 1023;
        int row = rem >> 3, seg = rem & 7;
        const __nv_bfloat16* src = (slab ? Qlo_g : Qhi_g) + (size_t)row * 64 + seg * 8;
        cp16(sbase + slab * (128 * AP) + row * AP + seg * 16, src);
    }
    CP_COMMIT();

    auto load_kv = [&](int t) {
        const int kv0 = t * 64;
        const uint32_t stg = sbase + AKV0 + (t & 1) * AKV_STAGE;
#pragma unroll
        for (int u = 0; u < 8; u++) {
            int idx = tid + u * 256;
            int slab = idx >> 9;
            int rem = idx & 511;
            int row = rem >> 3, seg = rem & 7;
            const __nv_bfloat16* src;
            if (slab == 0) src = Khi_g + (size_t)(kv0 + row) * 64 + seg * 8;
            else if (slab == 1) src = Klo_g + (size_t)(kv0 + row) * 64 + seg * 8;
            else if (slab == 2) src = Vthi_g + (size_t)row * 1024 + kv0 + seg * 8;
            else src = Vtlo_g + (size_t)row * 1024 + kv0 + seg * 8;
            cp16(stg + slab * (64 * AP) + row * AP + seg * 16, src);
        }
        CP_COMMIT();
    };

    const int nt = 2 * (qblk + 1);
    load_kv(0);
    load_kv(1);

    const int r = lane >> 2;
    const int tq = lane & 3;
    const int lrow = lane & 15;
    const int lkoff = (lane >> 4) * 16;
    const int qq0 = q0 + wrow + r;
    const int qq1 = qq0 + 8;
    const uint32_t qldm = sbase + (wrow + lrow) * AP + lkoff;

    float m0 = NINF, m1 = NINF, l0 = 0.f, l1 = 0.f;
    float oa[8][4];
#pragma unroll
    for (int nd = 0; nd < 8; nd++)
#pragma unroll
        for (int j = 0; j < 4; j++) oa[nd][j] = 0.f;

    for (int t = 0; t < nt; t++) {
        CP_WAIT1();
        __syncthreads();
        const int kv0 = t * 64;
        if (kv0 <= q0 + wrow + 15) {
            const uint32_t stg = sbase + AKV0 + (t & 1) * AKV_STAGE;
            const uint32_t vbase = stg + 2 * (64 * AP);
            // --- S = Q K^T ---
            float sa[8][4];
#pragma unroll
            for (int nj = 0; nj < 8; nj++)
#pragma unroll
                for (int j = 0; j < 4; j++) sa[nj][j] = 0.f;
#pragma unroll
            for (int ks = 0; ks < 4; ks++) {
                const uint32_t colb = ks * 32;
                uint32_t qh[4], ql[4];
                ldm_x4(qh, qldm + colb);
                ldm_x4(ql, qldm + colb + 128 * AP);
#pragma unroll
                for (int nj2 = 0; nj2 < 4; nj2++) {
                    uint32_t tt[4], kh0[2], kh1[2], kl0[2], kl1[2];
                    uint32_t ka = stg + (nj2 * 16 + lrow) * AP + colb + lkoff;
                    ldm_x4(tt, ka);
                    kh0[0] = tt[0]; kh0[1] = tt[2];
                    kh1[0] = tt[1]; kh1[1] = tt[3];
                    ldm_x4(tt, ka + 64 * AP);
                    kl0[0] = tt[0]; kl0[1] = tt[2];
                    kl1[0] = tt[1]; kl1[1] = tt[3];
                    mma_bf16(sa[2 * nj2], qh, kh0);
                    mma_bf16(sa[2 * nj2], qh, kl0);
                    mma_bf16(sa[2 * nj2], ql, kh0);
                    mma_bf16(sa[2 * nj2 + 1], qh, kh1);
                    mma_bf16(sa[2 * nj2 + 1], qh, kl1);
                    mma_bf16(sa[2 * nj2 + 1], ql, kh1);
                }
            }
            // --- softmax (online) ---
            float mloc0 = NINF, mloc1 = NINF;
#pragma unroll
            for (int nj = 0; nj < 8; nj++) {
                int c0 = kv0 + nj * 8 + 2 * tq;
                int c1 = c0 + 1;
                sa[nj][0] = (c0 <= qq0) ? sa[nj][0] * 0.125f + slope * (float)(c0 - qq0) : NINF;
                sa[nj][1] = (c1 <= qq0) ? sa[nj][1] * 0.125f + slope * (float)(c1 - qq0) : NINF;
                sa[nj][2] = (c0 <= qq1) ? sa[nj][2] * 0.125f + slope * (float)(c0 - qq1) : NINF;
                sa[nj][3] = (c1 <= qq1) ? sa[nj][3] * 0.125f + slope * (float)(c1 - qq1) : NINF;
                mloc0 = fmaxf(mloc0, fmaxf(sa[nj][0], sa[nj][1]));
                mloc1 = fmaxf(mloc1, fmaxf(sa[nj][2], sa[nj][3]));
            }
            mloc0 = fmaxf(mloc0, __shfl_xor_sync(0xffffffffu, mloc0, 1));
            mloc0 = fmaxf(mloc0, __shfl_xor_sync(0xffffffffu, mloc0, 2));
            mloc1 = fmaxf(mloc1, __shfl_xor_sync(0xffffffffu, mloc1, 1));
            mloc1 = fmaxf(mloc1, __shfl_xor_sync(0xffffffffu, mloc1, 2));
            float mn0 = fmaxf(m0, mloc0), mn1 = fmaxf(m1, mloc1);
            float corr0 = __expf(m0 - mn0), corr1 = __expf(m1 - mn1);
            m0 = mn0;
            m1 = mn1;
            float rs0 = 0.f, rs1 = 0.f;
            uint32_t ph[8][2], pl[8][2];
#pragma unroll
            for (int nj = 0; nj < 8; nj++) {
                float p00 = __expf(sa[nj][0] - mn0);
                float p01 = __expf(sa[nj][1] - mn0);
                float p10 = __expf(sa[nj][2] - mn1);
                float p11 = __expf(sa[nj][3] - mn1);
                rs0 += p00 + p01;
                rs1 += p10 + p11;
                split_pair(p00, p01, ph[nj][0], pl[nj][0]);
                split_pair(p10, p11, ph[nj][1], pl[nj][1]);
            }
            rs0 += __shfl_xor_sync(0xffffffffu, rs0, 1);
            rs0 += __shfl_xor_sync(0xffffffffu, rs0, 2);
            rs1 += __shfl_xor_sync(0xffffffffu, rs1, 1);
            rs1 += __shfl_xor_sync(0xffffffffu, rs1, 2);
            l0 = l0 * corr0 + rs0;
            l1 = l1 * corr1 + rs1;
#pragma unroll
            for (int nd = 0; nd < 8; nd++) {
                oa[nd][0] *= corr0;
                oa[nd][1] *= corr0;
                oa[nd][2] *= corr1;
                oa[nd][3] *= corr1;
            }
            // --- O += P V ---
#pragma unroll
            for (int ks = 0; ks < 4; ks++) {
                uint32_t ah[4] = {ph[2 * ks][0], ph[2 * ks][1], ph[2 * ks + 1][0], ph[2 * ks + 1][1]};
                uint32_t al[4] = {pl[2 * ks][0], pl[2 * ks][1], pl[2 * ks + 1][0], pl[2 * ks + 1][1]};
#pragma unroll
                for (int nd2 = 0; nd2 < 4; nd2++) {
                    uint32_t tt[4], vh0[2], vh1[2], vl0[2], vl1[2];
                    uint32_t va = vbase + (nd2 * 16 + lrow) * AP + ks * 32 + lkoff;
                    ldm_x4(tt, va);
                    vh0[0] = tt[0]; vh0[1] = tt[2];
                    vh1[0] = tt[1]; vh1[1] = tt[3];
                    ldm_x4(tt, va + 64 * AP);
                    vl0[0] = tt[0]; vl0[1] = tt[2];
                    vl1[0] = tt[1]; vl1[1] = tt[3];
                    mma_bf16(oa[2 * nd2], ah, vh0);
                    mma_bf16(oa[2 * nd2], ah, vl0);
                    mma_bf16(oa[2 * nd2], al, vh0);
                    mma_bf16(oa[2 * nd2 + 1], ah, vh1);
                    mma_bf16(oa[2 * nd2 + 1], ah, vl1);
                    mma_bf16(oa[2 * nd2 + 1], al, vh1);
                }
            }
        }
        __syncthreads();
        if (t + 2 < nt) load_kv(t + 2); else CP_COMMIT();
    }

    // Epilogue: normalize, split, store
    const float inv0 = 1.f / l0, inv1 = 1.f / l1;
    const size_t row0 = (size_t)(b * 1024 + q0 + wrow + r) * 2048 + h * 64;
    const size_t row1 = row0 + (size_t)8 * 2048;
#pragma unroll
    for (int nd = 0; nd < 8; nd++) {
        int d0 = nd * 8 + 2 * tq;
        uint32_t hh, ll;
        split_pair(oa[nd][0] * inv0, oa[nd][1] * inv0, hh, ll);
        *(uint32_t*)&g_At2hi[row0 + d0] = hh;
        *(uint32_t*)&g_At2lo[row0 + d0] = ll;
        split_pair(oa[nd][2] * inv1, oa[nd][3] * inv1, hh, ll);
        *(uint32_t*)&g_At2hi[row1 + d0] = hh;
        *(uint32_t*)&g_At2lo[row1 + d0] = ll;
    }
}

// ---------------------------------------------------------------------------
extern "C" void kernel_launch(void* const* d_in, const int* in_sizes, int n_in,
                              void* d_out, int out_size) {
    const float* inputs = (const float*)d_in[0];  // [4,1024,1024]
    const float* W_qkv  = (const float*)d_in[1];  // [1024,4096]
    const float* W_out  = (const float*)d_in[2];  // [2048,1024]
    float* out = (float*)d_out;                   // [4,1024,1024]

    cudaFuncSetAttribute(gemm_tc_kernel, cudaFuncAttributeMaxDynamicSharedMemorySize,
                         GSM_TOTAL);
    cudaFuncSetAttribute(attn_tc_kernel, cudaFuncAttributeMaxDynamicSharedMemorySize,
                         ATT_SMEM);

    __nv_bfloat16 *Ahi, *Alo, *Wqh, *Wql, *A2hi, *A2lo, *Woh, *Wol;
    float* qkv;
    cudaGetSymbolAddress((void**)&Ahi, g_Ahi);
    cudaGetSymbolAddress((void**)&Alo, g_Alo);
    cudaGetSymbolAddress((void**)&Wqh, g_Wqkv_hi);
    cudaGetSymbolAddress((void**)&Wql, g_Wqkv_lo);
    cudaGetSymbolAddress((void**)&A2hi, g_At2hi);
    cudaGetSymbolAddress((void**)&A2lo, g_At2lo);
    cudaGetSymbolAddress((void**)&Woh, g_Wout_hi);
    cudaGetSymbolAddress((void**)&Wol, g_Wout_lo);
    cudaGetSymbolAddress((void**)&qkv, g_qkv);

    // 1) split inputs; transpose-split both weight matrices
    split_kernel<<<(ROWS * HIDDEN / 4 + 255) / 256, 256>>>(inputs, Ahi, Alo,
                                                           ROWS * HIDDEN / 4);
    transpose_split_kernel<<<dim3(QKV_COLS / 32, HIDDEN / 32), dim3(32, 8)>>>(
        W_qkv, Wqh, Wql, HIDDEN, QKV_COLS);
    transpose_split_kernel<<<dim3(HIDDEN / 32, ATTN_COLS / 32), dim3(32, 8)>>>(
        W_out, Woh, Wol, ATTN_COLS, HIDDEN);

    // 2) QKV projection; fused epilogue writes Q/K splits + V fp32
    gemm_tc_kernel<<<dim3(QKV_COLS / 128, ROWS / 128), 256, GSM_TOTAL>>>(
        Ahi, Alo, Wqh, Wql, qkv, QKV_COLS, HIDDEN, 1);

    // 3) V transpose + split
    prep_vt_kernel<<<dim3(SEQL / 64, BATCH * 16), 256>>>();

    // 4) tensor-core attention -> g_At2hi/lo
    attn_tc_kernel<<<dim3(BATCH * 32, SEQL / 128), 256, ATT_SMEM>>>();

    // 5) Output projection -> out
    gemm_tc_kernel<<<dim3(HIDDEN / 128, ROWS / 128), 256, GSM_TOTAL>>>(
        A2hi, A2lo, Woh, Wol, out, HIDDEN, ATTN_COLS, 0);
}

// round 6
// speedup vs baseline: 1.4244x; 1.4244x over previous
#include <cuda_runtime.h>
#include <cuda_fp16.h>
#include <cstdint>

// Problem constants
#define BATCH 4
#define SEQL 1024
#define HIDDEN 1024
#define QKV_COLS 4096   // 2048 q + 1024 k + 1024 v
#define ATTN_COLS 2048  // 32*64
#define ROWS 4096       // BATCH*SEQL

// ---------------------------------------------------------------------------
// Scratch (__device__ globals; allocation-free rule)
// ---------------------------------------------------------------------------
__device__ float g_qkv[(size_t)ROWS * QKV_COLS];    // 64 MB
__device__ __half g_Ahi[(size_t)ROWS * HIDDEN];
__device__ __half g_Alo[(size_t)ROWS * HIDDEN];
__device__ __half g_Wqkv[(size_t)QKV_COLS * HIDDEN];   // [N,K] single fp16
__device__ __half g_At2hi[(size_t)ROWS * ATTN_COLS];   // attn out split
__device__ __half g_At2lo[(size_t)ROWS * ATTN_COLS];
__device__ __half g_Wout[(size_t)HIDDEN * ATTN_COLS];  // [N,K] single fp16
// attention operand splits
__device__ __half g_Qhi[(size_t)BATCH * 32 * SEQL * 64];   // [b,h,s,d]
__device__ __half g_Qlo[(size_t)BATCH * 32 * SEQL * 64];
__device__ __half g_Khi[(size_t)BATCH * 16 * SEQL * 64];   // [b,kvh,s,d]
__device__ __half g_Klo[(size_t)BATCH * 16 * SEQL * 64];
__device__ __half g_Vthi[(size_t)BATCH * 16 * 64 * SEQL];  // [b,kvh,d,s]
__device__ __half g_Vtlo[(size_t)BATCH * 16 * 64 * SEQL];

// ---------------------------------------------------------------------------
// PTX helpers (sm_80+ only — NO tcgen05; harness targets compute_103)
// ---------------------------------------------------------------------------
__device__ __forceinline__ uint32_t smem_u32(const void* p) {
    uint32_t a;
    asm("{ .reg .u64 t; cvta.to.shared.u64 t, %1; cvt.u32.u64 %0, t; }" : "=r"(a) : "l"(p));
    return a;
}
__device__ __forceinline__ void cp16(uint32_t dst, const void* src) {
    asm volatile("cp.async.cg.shared.global [%0], [%1], 16;" :: "r"(dst), "l"(src));
}
#define CP_COMMIT() asm volatile("cp.async.commit_group;" ::: "memory")
#define CP_WAIT1()  asm volatile("cp.async.wait_group 1;" ::: "memory")

__device__ __forceinline__ uint32_t lds32(uint32_t a) {
    uint32_t v;
    asm volatile("ld.shared.b32 %0, [%1];" : "=r"(v) : "r"(a));
    return v;
}
// mma.sync m16n8k16 row.col fp16 -> fp32 accumulate
__device__ __forceinline__ void mma_f16(float* d, const uint32_t* a, const uint32_t* b) {
    asm volatile(
        "mma.sync.aligned.m16n8k16.row.col.f32.f16.f16.f32 "
        "{%0,%1,%2,%3}, {%4,%5,%6,%7}, {%8,%9}, {%0,%1,%2,%3};"
        : "+f"(d[0]), "+f"(d[1]), "+f"(d[2]), "+f"(d[3])
        : "r"(a[0]), "r"(a[1]), "r"(a[2]), "r"(a[3]), "r"(b[0]), "r"(b[1]));
}
__device__ __forceinline__ uint32_t cvt_f16x2(float f0, float f1) {
    uint32_t r;
    asm("cvt.rn.f16x2.f32 %0, %1, %2;" : "=r"(r) : "f"(f1), "f"(f0));
    return r;
}
// split a float pair into hi/lo packed fp16x2
__device__ __forceinline__ void split_pair(float f0, float f1, uint32_t& hi, uint32_t& lo) {
    hi = cvt_f16x2(f0, f1);
    __half2 h2 = *reinterpret_cast<__half2*>(&hi);
    lo = cvt_f16x2(f0 - __low2float(h2), f1 - __high2float(h2));
}

// ---------------------------------------------------------------------------
// HMMA GEMM (fp16 asymmetric 2-product): C[M,N] = (Ahi+Alo)[M,K] * B[N,K]^T
// CTA tile 128x128, BK=32, 256 threads (8 warps: 2(M) x 4(N)).
// Smem row stride 40 halves (80B) -> conflict-free 32-bit fragment loads.
// ---------------------------------------------------------------------------
#define RS2 80                     // bytes per smem row (32 halves + 8 pad)
#define SLAB (128 * RS2)           // 10240 B per matrix slab
#define STAGE (3 * SLAB)           // Ahi, Alo, B = 30720 B
#define GSM_TOTAL (2 * STAGE)      // 61440 B

__global__ __launch_bounds__(256)
void gemm_tc_kernel(const __half* __restrict__ Ahi,
                    const __half* __restrict__ Alo,
                    const __half* __restrict__ B,
                    float* __restrict__ C, int Ndim, int Kdim) {
    extern __shared__ __align__(256) char smem[];
    const uint32_t sbase = smem_u32(smem);
    const int tid = threadIdx.x;
    const int lane = tid & 31;
    const int warp = tid >> 5;
    const int wm = warp & 1;
    const int wn = warp >> 1;
    const int brow = blockIdx.y * 128;
    const int bcol = blockIdx.x * 128;

    const __half* mats[3] = {Ahi, Alo, B};
    const int KT = Kdim >> 5;

    auto load_stage = [&](int t) {
        const int s = t & 1;
        const int k0 = t << 5;
        const uint32_t stg = sbase + s * STAGE;
#pragma unroll
        for (int m = 0; m < 3; m++) {
            const int rowbase = (m < 2) ? brow : bcol;
            const __half* base = mats[m];
#pragma unroll
            for (int u = 0; u < 2; u++) {
                int idx = tid + u * 256;
                int row = idx >> 2;
                int seg = idx & 3;
                const __half* src = base + (size_t)(rowbase + row) * Kdim + k0 + seg * 8;
                cp16(stg + m * SLAB + row * RS2 + seg * 16, src);
            }
        }
        CP_COMMIT();
    };

    float acc[4][4][4];
#pragma unroll
    for (int i = 0; i < 4; i++)
#pragma unroll
        for (int j = 0; j < 4; j++)
#pragma unroll
            for (int r = 0; r < 4; r++) acc[i][j][r] = 0.f;

    load_stage(0);
    if (KT > 1) load_stage(1); else CP_COMMIT();

    const int r0 = lane >> 2;
    const int cpair = (lane & 3) * 2;

    for (int t = 0; t < KT; t++) {
        CP_WAIT1();
        __syncthreads();
        const uint32_t stg = sbase + (t & 1) * STAGE;
        const uint32_t aHi = stg + (wm * 64) * RS2;
        const uint32_t bB = stg + 2 * SLAB + (wn * 32) * RS2;

#pragma unroll
        for (int ks = 0; ks < 2; ks++) {
            const uint32_t colb = ks * 32 + cpair * 2;
            uint32_t ahi[4][4], alo[4][4], bb[4][2];
#pragma unroll
            for (int mi = 0; mi < 4; mi++) {
                uint32_t rb = (mi * 16 + r0) * RS2;
                ahi[mi][0] = lds32(aHi + rb + colb);
                ahi[mi][1] = lds32(aHi + rb + 8 * RS2 + colb);
                ahi[mi][2] = lds32(aHi + rb + colb + 16);
                ahi[mi][3] = lds32(aHi + rb + 8 * RS2 + colb + 16);
                alo[mi][0] = lds32(aHi + SLAB + rb + colb);
                alo[mi][1] = lds32(aHi + SLAB + rb + 8 * RS2 + colb);
                alo[mi][2] = lds32(aHi + SLAB + rb + colb + 16);
                alo[mi][3] = lds32(aHi + SLAB + rb + 8 * RS2 + colb + 16);
            }
#pragma unroll
            for (int nj = 0; nj < 4; nj++) {
                uint32_t rb = (nj * 8 + r0) * RS2;
                bb[nj][0] = lds32(bB + rb + colb);
                bb[nj][1] = lds32(bB + rb + colb + 16);
            }
#pragma unroll
            for (int mi = 0; mi < 4; mi++)
#pragma unroll
                for (int nj = 0; nj < 4; nj++) {
                    mma_f16(acc[mi][nj], ahi[mi], bb[nj]);
                    mma_f16(acc[mi][nj], alo[mi], bb[nj]);
                }
        }
        __syncthreads();
        if (t + 2 < KT) load_stage(t + 2); else CP_COMMIT();
    }

#pragma unroll
    for (int mi = 0; mi < 4; mi++) {
        int row = brow + wm * 64 + mi * 16 + r0;
#pragma unroll
        for (int nj = 0; nj < 4; nj++) {
            int col = bcol + wn * 32 + nj * 8 + cpair;
            *(float2*)(C + (size_t)row * Ndim + col) =
                make_float2(acc[mi][nj][0], acc[mi][nj][1]);
            *(float2*)(C + (size_t)(row + 8) * Ndim + col) =
                make_float2(acc[mi][nj][2], acc[mi][nj][3]);
        }
    }
}

// ---------------------------------------------------------------------------
// fp32 -> fp16 hi/lo elementwise split (GEMM A operands)
// ---------------------------------------------------------------------------
__global__ __launch_bounds__(256) void split_kernel(const float* __restrict__ x,
                                                    __half* __restrict__ hi,
                                                    __half* __restrict__ lo,
                                                    int n4) {
    int i = blockIdx.x * blockDim.x + threadIdx.x;
    if (i >= n4) return;
    float4 v = ((const float4*)x)[i];
    uint32_t h0, l0, h1, l1;
    split_pair(v.x, v.y, h0, l0);
    split_pair(v.z, v.w, h1, l1);
    ((uint2*)hi)[i] = make_uint2(h0, h1);
    ((uint2*)lo)[i] = make_uint2(l0, l1);
}

// ---------------------------------------------------------------------------
// W[K,N] fp32 -> Wt[N,K] single fp16 (tiled transpose)
// ---------------------------------------------------------------------------
__global__ __launch_bounds__(256) void transpose_h_kernel(
    const float* __restrict__ W, __half* __restrict__ Wt, int K, int N) {
    __shared__ float t[32][33];
    int k0 = blockIdx.y * 32, n0 = blockIdx.x * 32;
    int tx = threadIdx.x, ty = threadIdx.y;  // (32, 8)
#pragma unroll
    for (int j = 0; j < 4; j++)
        t[ty + j * 8][tx] = W[(size_t)(k0 + ty + j * 8) * N + n0 + tx];
    __syncthreads();
#pragma unroll
    for (int j = 0; j < 4; j++)
        Wt[(size_t)(n0 + ty + j * 8) * K + k0 + tx] = __float2half_rn(t[tx][ty + j * 8]);
}

// ---------------------------------------------------------------------------
// Prep: split g_qkv into attention operand layouts (fp16 hi/lo)
// ---------------------------------------------------------------------------
__global__ __launch_bounds__(256) void prep_q_kernel() {
    int i = blockIdx.x * 256 + threadIdx.x;
    int o = i * 4;
    int d = o & 63, s = (o >> 6) & 1023, h = (o >> 16) & 31, b = o >> 21;
    float4 v = *(const float4*)&g_qkv[((size_t)(b * 1024 + s)) * 4096 + h * 64 + d];
    uint32_t h0, l0, h1, l1;
    split_pair(v.x, v.y, h0, l0);
    split_pair(v.z, v.w, h1, l1);
    *(uint2*)&g_Qhi[o] = make_uint2(h0, h1);
    *(uint2*)&g_Qlo[o] = make_uint2(l0, l1);
}

__global__ __launch_bounds__(256) void prep_k_kernel() {
    int i = blockIdx.x * 256 + threadIdx.x;
    int o = i * 4;
    int d = o & 63, s = (o >> 6) & 1023, kvh = (o >> 16) & 15, b = o >> 20;
    float4 v = *(const float4*)&g_qkv[((size_t)(b * 1024 + s)) * 4096 + 2048 + kvh * 64 + d];
    uint32_t h0, l0, h1, l1;
    split_pair(v.x, v.y, h0, l0);
    split_pair(v.z, v.w, h1, l1);
    *(uint2*)&g_Khi[o] = make_uint2(h0, h1);
    *(uint2*)&g_Klo[o] = make_uint2(l0, l1);
}

__global__ __launch_bounds__(256) void prep_vt_kernel() {
    __shared__ float tile[64][65];
    int s0 = blockIdx.x * 64;
    int bk = blockIdx.y;               // b*16 + kvh
    int b = bk >> 4, kvh = bk & 15;
    int tid = threadIdx.x;
#pragma unroll
    for (int u = 0; u < 4; u++) {
        int lin = tid + u * 256;
        int row = lin >> 4, c4 = lin & 15;
        float4 v = *(const float4*)&g_qkv[((size_t)(b * 1024 + s0 + row)) * 4096 +
                                          3072 + kvh * 64 + c4 * 4];
        tile[row][c4 * 4 + 0] = v.x;
        tile[row][c4 * 4 + 1] = v.y;
        tile[row][c4 * 4 + 2] = v.z;
        tile[row][c4 * 4 + 3] = v.w;
    }
    __syncthreads();
#pragma unroll
    for (int u = 0; u < 4; u++) {
        int lin = tid + u * 256;
        int d = lin >> 4, c4 = lin & 15;
        float f0 = tile[c4 * 4 + 0][d], f1 = tile[c4 * 4 + 1][d];
        float f2 = tile[c4 * 4 + 2][d], f3 = tile[c4 * 4 + 3][d];
        uint32_t h0, l0, h1, l1;
        split_pair(f0, f1, h0, l0);
        split_pair(f2, f3, h1, l1);
        size_t o = ((size_t)bk * 64 + d) * 1024 + s0 + c4 * 4;
        *(uint2*)&g_Vthi[o] = make_uint2(h0, h1);
        *(uint2*)&g_Vtlo[o] = make_uint2(l0, l1);
    }
}

// ---------------------------------------------------------------------------
// Tensor-core flash attention, fp16 hi/lo 3-product split (round-4 structure).
// ---------------------------------------------------------------------------
#define AP 144                    // smem pitch bytes (64 halves + 8 pad)
#define AKV0 (2 * 128 * AP)
#define AKV_STAGE (4 * 64 * AP)
#define ATT_SMEM (AKV0 + 2 * AKV_STAGE)

__global__ __launch_bounds__(256) void attn_tc_kernel() {
    extern __shared__ __align__(256) char smem[];
    const uint32_t sbase = smem_u32(smem);
    const int tid = threadIdx.x;
    const int lane = tid & 31;
    const int warp = tid >> 5;
    const int bh = blockIdx.x;
    const int b = bh >> 5;
    const int h = bh & 31;
    const int kvh = h >> 1;
    const int qblk = (int)gridDim.y - 1 - (int)blockIdx.y;
    const int q0 = qblk * 128;
    const int wrow = warp * 16;
    const float slope = exp2f(-0.25f * (float)(h + 1));
    const float NINF = -__int_as_float(0x7f800000);

    const __half* Qhi_g = g_Qhi + ((size_t)(b * 32 + h) * 1024 + q0) * 64;
    const __half* Qlo_g = g_Qlo + ((size_t)(b * 32 + h) * 1024 + q0) * 64;
    const __half* Khi_g = g_Khi + (size_t)(b * 16 + kvh) * 1024 * 64;
    const __half* Klo_g = g_Klo + (size_t)(b * 16 + kvh) * 1024 * 64;
    const __half* Vthi_g = g_Vthi + (size_t)(b * 16 + kvh) * 64 * 1024;
    const __half* Vtlo_g = g_Vtlo + (size_t)(b * 16 + kvh) * 64 * 1024;

#pragma unroll
    for (int u = 0; u < 8; u++) {
        int idx = tid + u * 256;
        int slab = idx >> 10;
        int rem = idx & 1023;
        int row = rem >> 3, seg = rem & 7;
        const __half* src = (slab ? Qlo_g : Qhi_g) + (size_t)row * 64 + seg * 8;
        cp16(sbase + slab * (128 * AP) + row * AP + seg * 16, src);
    }
    CP_COMMIT();

    auto load_kv = [&](int t) {
        const int kv0 = t * 64;
        const uint32_t stg = sbase + AKV0 + (t & 1) * AKV_STAGE;
#pragma unroll
        for (int u = 0; u < 8; u++) {
            int idx = tid + u * 256;
            int slab = idx >> 9;
            int rem = idx & 511;
            int row = rem >> 3, seg = rem & 7;
            const __half* src;
            if (slab == 0) src = Khi_g + (size_t)(kv0 + row) * 64 + seg * 8;
            else if (slab == 1) src = Klo_g + (size_t)(kv0 + row) * 64 + seg * 8;
            else if (slab == 2) src = Vthi_g + (size_t)row * 1024 + kv0 + seg * 8;
            else src = Vtlo_g + (size_t)row * 1024 + kv0 + seg * 8;
            cp16(stg + slab * (64 * AP) + row * AP + seg * 16, src);
        }
        CP_COMMIT();
    };

    const int nt = 2 * (qblk + 1);
    load_kv(0);
    load_kv(1);

    const int r = lane >> 2;
    const int tq = lane & 3;
    const int qq0 = q0 + wrow + r;
    const int qq1 = qq0 + 8;
    const uint32_t qrow_hi = sbase + (wrow + r) * AP + tq * 4;
    const uint32_t qrow_lo = qrow_hi + 128 * AP;

    float m0 = NINF, m1 = NINF, l0 = 0.f, l1 = 0.f;
    float oa[8][4];
#pragma unroll
    for (int nd = 0; nd < 8; nd++)
#pragma unroll
        for (int j = 0; j < 4; j++) oa[nd][j] = 0.f;

    for (int t = 0; t < nt; t++) {
        CP_WAIT1();
        __syncthreads();
        const int kv0 = t * 64;
        if (kv0 <= q0 + wrow + 15) {
            const uint32_t stg = sbase + AKV0 + (t & 1) * AKV_STAGE;
            const uint32_t vbase = stg + 2 * (64 * AP);
            // --- S = Q K^T (3-product) ---
            float sa[8][4];
#pragma unroll
            for (int nj = 0; nj < 8; nj++)
#pragma unroll
                for (int j = 0; j < 4; j++) sa[nj][j] = 0.f;
#pragma unroll
            for (int ks = 0; ks < 4; ks++) {
                const uint32_t colb = ks * 32;
                uint32_t qh[4], ql[4];
                qh[0] = lds32(qrow_hi + colb);
                qh[1] = lds32(qrow_hi + 8 * AP + colb);
                qh[2] = lds32(qrow_hi + colb + 16);
                qh[3] = lds32(qrow_hi + 8 * AP + colb + 16);
                ql[0] = lds32(qrow_lo + colb);
                ql[1] = lds32(qrow_lo + 8 * AP + colb);
                ql[2] = lds32(qrow_lo + colb + 16);
                ql[3] = lds32(qrow_lo + 8 * AP + colb + 16);
#pragma unroll
                for (int nj = 0; nj < 8; nj++) {
                    uint32_t ka = stg + (nj * 8 + r) * AP + colb + tq * 4;
                    uint32_t kh[2], kl[2];
                    kh[0] = lds32(ka);
                    kh[1] = lds32(ka + 16);
                    kl[0] = lds32(ka + 64 * AP);
                    kl[1] = lds32(ka + 64 * AP + 16);
                    mma_f16(sa[nj], qh, kh);
                    mma_f16(sa[nj], qh, kl);
                    mma_f16(sa[nj], ql, kh);
                }
            }
            // --- softmax (online) ---
            float mloc0 = NINF, mloc1 = NINF;
#pragma unroll
            for (int nj = 0; nj < 8; nj++) {
                int c0 = kv0 + nj * 8 + 2 * tq;
                int c1 = c0 + 1;
                sa[nj][0] = (c0 <= qq0) ? sa[nj][0] * 0.125f + slope * (float)(c0 - qq0) : NINF;
                sa[nj][1] = (c1 <= qq0) ? sa[nj][1] * 0.125f + slope * (float)(c1 - qq0) : NINF;
                sa[nj][2] = (c0 <= qq1) ? sa[nj][2] * 0.125f + slope * (float)(c0 - qq1) : NINF;
                sa[nj][3] = (c1 <= qq1) ? sa[nj][3] * 0.125f + slope * (float)(c1 - qq1) : NINF;
                mloc0 = fmaxf(mloc0, fmaxf(sa[nj][0], sa[nj][1]));
                mloc1 = fmaxf(mloc1, fmaxf(sa[nj][2], sa[nj][3]));
            }
            mloc0 = fmaxf(mloc0, __shfl_xor_sync(0xffffffffu, mloc0, 1));
            mloc0 = fmaxf(mloc0, __shfl_xor_sync(0xffffffffu, mloc0, 2));
            mloc1 = fmaxf(mloc1, __shfl_xor_sync(0xffffffffu, mloc1, 1));
            mloc1 = fmaxf(mloc1, __shfl_xor_sync(0xffffffffu, mloc1, 2));
            float mn0 = fmaxf(m0, mloc0), mn1 = fmaxf(m1, mloc1);
            float corr0 = __expf(m0 - mn0), corr1 = __expf(m1 - mn1);
            m0 = mn0;
            m1 = mn1;
            float rs0 = 0.f, rs1 = 0.f;
            uint32_t ph[8][2], pl[8][2];
#pragma unroll
            for (int nj = 0; nj < 8; nj++) {
                float p00 = __expf(sa[nj][0] - mn0);
                float p01 = __expf(sa[nj][1] - mn0);
                float p10 = __expf(sa[nj][2] - mn1);
                float p11 = __expf(sa[nj][3] - mn1);
                rs0 += p00 + p01;
                rs1 += p10 + p11;
                split_pair(p00, p01, ph[nj][0], pl[nj][0]);
                split_pair(p10, p11, ph[nj][1], pl[nj][1]);
            }
            rs0 += __shfl_xor_sync(0xffffffffu, rs0, 1);
            rs0 += __shfl_xor_sync(0xffffffffu, rs0, 2);
            rs1 += __shfl_xor_sync(0xffffffffu, rs1, 1);
            rs1 += __shfl_xor_sync(0xffffffffu, rs1, 2);
            l0 = l0 * corr0 + rs0;
            l1 = l1 * corr1 + rs1;
#pragma unroll
            for (int nd = 0; nd < 8; nd++) {
                oa[nd][0] *= corr0;
                oa[nd][1] *= corr0;
                oa[nd][2] *= corr1;
                oa[nd][3] *= corr1;
            }
            // --- O += P V (3-product) ---
#pragma unroll
            for (int ks = 0; ks < 4; ks++) {
                uint32_t ah[4] = {ph[2 * ks][0], ph[2 * ks][1], ph[2 * ks + 1][0], ph[2 * ks + 1][1]};
                uint32_t al[4] = {pl[2 * ks][0], pl[2 * ks][1], pl[2 * ks + 1][0], pl[2 * ks + 1][1]};
#pragma unroll
                for (int nd = 0; nd < 8; nd++) {
                    uint32_t va = vbase + (nd * 8 + r) * AP + ks * 32 + tq * 4;
                    uint32_t vh[2], vl[2];
                    vh[0] = lds32(va);
                    vh[1] = lds32(va + 16);
                    vl[0] = lds32(va + 64 * AP);
                    vl[1] = lds32(va + 64 * AP + 16);
                    mma_f16(oa[nd], ah, vh);
                    mma_f16(oa[nd], ah, vl);
                    mma_f16(oa[nd], al, vh);
                }
            }
        }
        __syncthreads();
        if (t + 2 < nt) load_kv(t + 2); else CP_COMMIT();
    }

    // Epilogue: normalize, split fp16 hi/lo, store
    const float inv0 = 1.f / l0, inv1 = 1.f / l1;
    const size_t row0 = (size_t)(b * 1024 + q0 + wrow + r) * 2048 + h * 64;
    const size_t row1 = row0 + (size_t)8 * 2048;
#pragma unroll
    for (int nd = 0; nd < 8; nd++) {
        int d0 = nd * 8 + 2 * tq;
        uint32_t hh, ll;
        split_pair(oa[nd][0] * inv0, oa[nd][1] * inv0, hh, ll);
        *(uint32_t*)&g_At2hi[row0 + d0] = hh;
        *(uint32_t*)&g_At2lo[row0 + d0] = ll;
        split_pair(oa[nd][2] * inv1, oa[nd][3] * inv1, hh, ll);
        *(uint32_t*)&g_At2hi[row1 + d0] = hh;
        *(uint32_t*)&g_At2lo[row1 + d0] = ll;
    }
}

// ---------------------------------------------------------------------------
extern "C" void kernel_launch(void* const* d_in, const int* in_sizes, int n_in,
                              void* d_out, int out_size) {
    const float* inputs = (const float*)d_in[0];  // [4,1024,1024]
    const float* W_qkv  = (const float*)d_in[1];  // [1024,4096]
    const float* W_out  = (const float*)d_in[2];  // [2048,1024]
    float* out = (float*)d_out;                   // [4,1024,1024]

    cudaFuncSetAttribute(gemm_tc_kernel, cudaFuncAttributeMaxDynamicSharedMemorySize,
                         GSM_TOTAL);
    cudaFuncSetAttribute(attn_tc_kernel, cudaFuncAttributeMaxDynamicSharedMemorySize,
                         ATT_SMEM);

    __half *Ahi, *Alo, *Wq, *A2hi, *A2lo, *Wo;
    float* qkv;
    cudaGetSymbolAddress((void**)&Ahi, g_Ahi);
    cudaGetSymbolAddress((void**)&Alo, g_Alo);
    cudaGetSymbolAddress((void**)&Wq, g_Wqkv);
    cudaGetSymbolAddress((void**)&A2hi, g_At2hi);
    cudaGetSymbolAddress((void**)&A2lo, g_At2lo);
    cudaGetSymbolAddress((void**)&Wo, g_Wout);
    cudaGetSymbolAddress((void**)&qkv, g_qkv);

    // 1) split inputs; transpose both weight matrices to single fp16 [N,K]
    split_kernel<<<(ROWS * HIDDEN / 4 + 255) / 256, 256>>>(inputs, Ahi, Alo,
                                                           ROWS * HIDDEN / 4);
    transpose_h_kernel<<<dim3(QKV_COLS / 32, HIDDEN / 32), dim3(32, 8)>>>(
        W_qkv, Wq, HIDDEN, QKV_COLS);
    transpose_h_kernel<<<dim3(HIDDEN / 32, ATTN_COLS / 32), dim3(32, 8)>>>(
        W_out, Wo, ATTN_COLS, HIDDEN);

    // 2) QKV projection (2-product) -> g_qkv fp32
    gemm_tc_kernel<<<dim3(QKV_COLS / 128, ROWS / 128), 256, GSM_TOTAL>>>(
        Ahi, Alo, Wq, qkv, QKV_COLS, HIDDEN);

    // 3) prep attention operands (fp16 split + V transpose)
    prep_q_kernel<<<(BATCH * 32 * SEQL * 64 / 4) / 256, 256>>>();
    prep_k_kernel<<<(BATCH * 16 * SEQL * 64 / 4) / 256, 256>>>();
    prep_vt_kernel<<<dim3(SEQL / 64, BATCH * 16), 256>>>();

    // 4) tensor-core attention -> g_At2hi/lo (pre-split fp16)
    attn_tc_kernel<<<dim3(BATCH * 32, SEQL / 128), 256, ATT_SMEM>>>();

    // 5) Output projection (2-product) -> out
    gemm_tc_kernel<<<dim3(HIDDEN / 128, ROWS / 128), 256, GSM_TOTAL>>>(
        A2hi, A2lo, Wo, out, HIDDEN, ATTN_COLS);
}

// round 7
// speedup vs baseline: 1.6236x; 1.1398x over previous
#include <cuda_runtime.h>
#include <cuda_fp16.h>
#include <cstdint>

// Problem constants
#define BATCH 4
#define SEQL 1024
#define HIDDEN 1024
#define QKV_COLS 4096   // 2048 q + 1024 k + 1024 v
#define ATTN_COLS 2048  // 32*64
#define ROWS 4096       // BATCH*SEQL

// ---------------------------------------------------------------------------
// Scratch (__device__ globals; allocation-free rule)
// ---------------------------------------------------------------------------
__device__ float g_qkv[(size_t)ROWS * QKV_COLS];    // 64 MB
__device__ __half g_Ahi[(size_t)ROWS * HIDDEN];
__device__ __half g_Alo[(size_t)ROWS * HIDDEN];
__device__ __half g_Wqkv[(size_t)QKV_COLS * HIDDEN];   // [N,K] single fp16
__device__ __half g_At2hi[(size_t)ROWS * ATTN_COLS];   // attn out split
__device__ __half g_At2lo[(size_t)ROWS * ATTN_COLS];
__device__ __half g_Wout[(size_t)HIDDEN * ATTN_COLS];  // [N,K] single fp16
// attention operands
__device__ __half g_Qhi[(size_t)BATCH * 32 * SEQL * 64];  // [b,h,s,d] split
__device__ __half g_Qlo[(size_t)BATCH * 32 * SEQL * 64];
__device__ __half g_K[(size_t)BATCH * 16 * SEQL * 64];    // [b,kvh,s,d] single
__device__ __half g_Vt[(size_t)BATCH * 16 * 64 * SEQL];   // [b,kvh,d,s] single

// ---------------------------------------------------------------------------
// PTX helpers (sm_80+ only — NO tcgen05; harness targets compute_103)
// ---------------------------------------------------------------------------
__device__ __forceinline__ uint32_t smem_u32(const void* p) {
    uint32_t a;
    asm("{ .reg .u64 t; cvta.to.shared.u64 t, %1; cvt.u32.u64 %0, t; }" : "=r"(a) : "l"(p));
    return a;
}
__device__ __forceinline__ void cp16(uint32_t dst, const void* src) {
    asm volatile("cp.async.cg.shared.global [%0], [%1], 16;" :: "r"(dst), "l"(src));
}
#define CP_COMMIT() asm volatile("cp.async.commit_group;" ::: "memory")
#define CP_WAIT1()  asm volatile("cp.async.wait_group 1;" ::: "memory")

__device__ __forceinline__ uint32_t lds32(uint32_t a) {
    uint32_t v;
    asm volatile("ld.shared.b32 %0, [%1];" : "=r"(v) : "r"(a));
    return v;
}
// mma.sync m16n8k16 row.col fp16 -> fp32 accumulate
__device__ __forceinline__ void mma_f16(float* d, const uint32_t* a, const uint32_t* b) {
    asm volatile(
        "mma.sync.aligned.m16n8k16.row.col.f32.f16.f16.f32 "
        "{%0,%1,%2,%3}, {%4,%5,%6,%7}, {%8,%9}, {%0,%1,%2,%3};"
        : "+f"(d[0]), "+f"(d[1]), "+f"(d[2]), "+f"(d[3])
        : "r"(a[0]), "r"(a[1]), "r"(a[2]), "r"(a[3]), "r"(b[0]), "r"(b[1]));
}
__device__ __forceinline__ uint32_t cvt_f16x2(float f0, float f1) {
    uint32_t r;
    asm("cvt.rn.f16x2.f32 %0, %1, %2;" : "=r"(r) : "f"(f1), "f"(f0));
    return r;
}
// split a float pair into hi/lo packed fp16x2
__device__ __forceinline__ void split_pair(float f0, float f1, uint32_t& hi, uint32_t& lo) {
    hi = cvt_f16x2(f0, f1);
    __half2 h2 = *reinterpret_cast<__half2*>(&hi);
    lo = cvt_f16x2(f0 - __low2float(h2), f1 - __high2float(h2));
}

// ---------------------------------------------------------------------------
// HMMA GEMM (fp16 asymmetric 2-product): C[M,N] = (Ahi+Alo)[M,K] * B[N,K]^T
// CTA tile 128x128, BK=32, 256 threads (8 warps: 2(M) x 4(N)).
// MMA issue: full hi pass then full lo pass -> dependent MMAs 16 apart.
// ---------------------------------------------------------------------------
#define RS2 80                     // bytes per smem row (32 halves + 8 pad)
#define SLAB (128 * RS2)           // 10240 B per matrix slab
#define STAGE (3 * SLAB)           // Ahi, Alo, B = 30720 B
#define GSM_TOTAL (2 * STAGE)      // 61440 B

__global__ __launch_bounds__(256)
void gemm_tc_kernel(const __half* __restrict__ Ahi,
                    const __half* __restrict__ Alo,
                    const __half* __restrict__ B,
                    float* __restrict__ C, int Ndim, int Kdim) {
    extern __shared__ __align__(256) char smem[];
    const uint32_t sbase = smem_u32(smem);
    const int tid = threadIdx.x;
    const int lane = tid & 31;
    const int warp = tid >> 5;
    const int wm = warp & 1;
    const int wn = warp >> 1;
    const int brow = blockIdx.y * 128;
    const int bcol = blockIdx.x * 128;

    const __half* mats[3] = {Ahi, Alo, B};
    const int KT = Kdim >> 5;

    auto load_stage = [&](int t) {
        const int s = t & 1;
        const int k0 = t << 5;
        const uint32_t stg = sbase + s * STAGE;
#pragma unroll
        for (int m = 0; m < 3; m++) {
            const int rowbase = (m < 2) ? brow : bcol;
            const __half* base = mats[m];
#pragma unroll
            for (int u = 0; u < 2; u++) {
                int idx = tid + u * 256;
                int row = idx >> 2;
                int seg = idx & 3;
                const __half* src = base + (size_t)(rowbase + row) * Kdim + k0 + seg * 8;
                cp16(stg + m * SLAB + row * RS2 + seg * 16, src);
            }
        }
        CP_COMMIT();
    };

    float acc[4][4][4];
#pragma unroll
    for (int i = 0; i < 4; i++)
#pragma unroll
        for (int j = 0; j < 4; j++)
#pragma unroll
            for (int r = 0; r < 4; r++) acc[i][j][r] = 0.f;

    load_stage(0);
    if (KT > 1) load_stage(1); else CP_COMMIT();

    const int r0 = lane >> 2;
    const int cpair = (lane & 3) * 2;

    for (int t = 0; t < KT; t++) {
        CP_WAIT1();
        __syncthreads();
        const uint32_t stg = sbase + (t & 1) * STAGE;
        const uint32_t aHi = stg + (wm * 64) * RS2;
        const uint32_t bB = stg + 2 * SLAB + (wn * 32) * RS2;

#pragma unroll
        for (int ks = 0; ks < 2; ks++) {
            const uint32_t colb = ks * 32 + cpair * 2;
            uint32_t ahi[4][4], alo[4][4], bb[4][2];
#pragma unroll
            for (int mi = 0; mi < 4; mi++) {
                uint32_t rb = (mi * 16 + r0) * RS2;
                ahi[mi][0] = lds32(aHi + rb + colb);
                ahi[mi][1] = lds32(aHi + rb + 8 * RS2 + colb);
                ahi[mi][2] = lds32(aHi + rb + colb + 16);
                ahi[mi][3] = lds32(aHi + rb + 8 * RS2 + colb + 16);
                alo[mi][0] = lds32(aHi + SLAB + rb + colb);
                alo[mi][1] = lds32(aHi + SLAB + rb + 8 * RS2 + colb);
                alo[mi][2] = lds32(aHi + SLAB + rb + colb + 16);
                alo[mi][3] = lds32(aHi + SLAB + rb + 8 * RS2 + colb + 16);
            }
#pragma unroll
            for (int nj = 0; nj < 4; nj++) {
                uint32_t rb = (nj * 8 + r0) * RS2;
                bb[nj][0] = lds32(bB + rb + colb);
                bb[nj][1] = lds32(bB + rb + colb + 16);
            }
            // hi pass
#pragma unroll
            for (int mi = 0; mi < 4; mi++)
#pragma unroll
                for (int nj = 0; nj < 4; nj++)
                    mma_f16(acc[mi][nj], ahi[mi], bb[nj]);
            // lo pass
#pragma unroll
            for (int mi = 0; mi < 4; mi++)
#pragma unroll
                for (int nj = 0; nj < 4; nj++)
                    mma_f16(acc[mi][nj], alo[mi], bb[nj]);
        }
        __syncthreads();
        if (t + 2 < KT) load_stage(t + 2); else CP_COMMIT();
    }

#pragma unroll
    for (int mi = 0; mi < 4; mi++) {
        int row = brow + wm * 64 + mi * 16 + r0;
#pragma unroll
        for (int nj = 0; nj < 4; nj++) {
            int col = bcol + wn * 32 + nj * 8 + cpair;
            *(float2*)(C + (size_t)row * Ndim + col) =
                make_float2(acc[mi][nj][0], acc[mi][nj][1]);
            *(float2*)(C + (size_t)(row + 8) * Ndim + col) =
                make_float2(acc[mi][nj][2], acc[mi][nj][3]);
        }
    }
}

// ---------------------------------------------------------------------------
// fp32 -> fp16 hi/lo elementwise split (GEMM A operands)
// ---------------------------------------------------------------------------
__global__ __launch_bounds__(256) void split_kernel(const float* __restrict__ x,
                                                    __half* __restrict__ hi,
                                                    __half* __restrict__ lo,
                                                    int n4) {
    int i = blockIdx.x * blockDim.x + threadIdx.x;
    if (i >= n4) return;
    float4 v = ((const float4*)x)[i];
    uint32_t h0, l0, h1, l1;
    split_pair(v.x, v.y, h0, l0);
    split_pair(v.z, v.w, h1, l1);
    ((uint2*)hi)[i] = make_uint2(h0, h1);
    ((uint2*)lo)[i] = make_uint2(l0, l1);
}

// ---------------------------------------------------------------------------
// W[K,N] fp32 -> Wt[N,K] single fp16 (tiled transpose)
// ---------------------------------------------------------------------------
__global__ __launch_bounds__(256) void transpose_h_kernel(
    const float* __restrict__ W, __half* __restrict__ Wt, int K, int N) {
    __shared__ float t[32][33];
    int k0 = blockIdx.y * 32, n0 = blockIdx.x * 32;
    int tx = threadIdx.x, ty = threadIdx.y;  // (32, 8)
#pragma unroll
    for (int j = 0; j < 4; j++)
        t[ty + j * 8][tx] = W[(size_t)(k0 + ty + j * 8) * N + n0 + tx];
    __syncthreads();
#pragma unroll
    for (int j = 0; j < 4; j++)
        Wt[(size_t)(n0 + ty + j * 8) * K + k0 + tx] = __float2half_rn(t[tx][ty + j * 8]);
}

// ---------------------------------------------------------------------------
// Prep kernels
// ---------------------------------------------------------------------------
__global__ __launch_bounds__(256) void prep_q_kernel() {
    int i = blockIdx.x * 256 + threadIdx.x;
    int o = i * 4;
    int d = o & 63, s = (o >> 6) & 1023, h = (o >> 16) & 31, b = o >> 21;
    float4 v = *(const float4*)&g_qkv[((size_t)(b * 1024 + s)) * 4096 + h * 64 + d];
    uint32_t h0, l0, h1, l1;
    split_pair(v.x, v.y, h0, l0);
    split_pair(v.z, v.w, h1, l1);
    *(uint2*)&g_Qhi[o] = make_uint2(h0, h1);
    *(uint2*)&g_Qlo[o] = make_uint2(l0, l1);
}

__global__ __launch_bounds__(256) void prep_k_kernel() {
    int i = blockIdx.x * 256 + threadIdx.x;
    int o = i * 4;
    int d = o & 63, s = (o >> 6) & 1023, kvh = (o >> 16) & 15, b = o >> 20;
    float4 v = *(const float4*)&g_qkv[((size_t)(b * 1024 + s)) * 4096 + 2048 + kvh * 64 + d];
    uint32_t p0 = cvt_f16x2(v.x, v.y);
    uint32_t p1 = cvt_f16x2(v.z, v.w);
    *(uint2*)&g_K[o] = make_uint2(p0, p1);
}

__global__ __launch_bounds__(256) void prep_vt_kernel() {
    __shared__ float tile[64][65];
    int s0 = blockIdx.x * 64;
    int bk = blockIdx.y;               // b*16 + kvh
    int b = bk >> 4, kvh = bk & 15;
    int tid = threadIdx.x;
#pragma unroll
    for (int u = 0; u < 4; u++) {
        int lin = tid + u * 256;
        int row = lin >> 4, c4 = lin & 15;
        float4 v = *(const float4*)&g_qkv[((size_t)(b * 1024 + s0 + row)) * 4096 +
                                          3072 + kvh * 64 + c4 * 4];
        tile[row][c4 * 4 + 0] = v.x;
        tile[row][c4 * 4 + 1] = v.y;
        tile[row][c4 * 4 + 2] = v.z;
        tile[row][c4 * 4 + 3] = v.w;
    }
    __syncthreads();
#pragma unroll
    for (int u = 0; u < 4; u++) {
        int lin = tid + u * 256;
        int d = lin >> 4, c4 = lin & 15;
        uint32_t p0 = cvt_f16x2(tile[c4 * 4 + 0][d], tile[c4 * 4 + 1][d]);
        uint32_t p1 = cvt_f16x2(tile[c4 * 4 + 2][d], tile[c4 * 4 + 3][d]);
        size_t o = ((size_t)bk * 64 + d) * 1024 + s0 + c4 * 4;
        *(uint2*)&g_Vt[o] = make_uint2(p0, p1);
    }
}

// ---------------------------------------------------------------------------
// Tensor-core flash attention, fp16 asymmetric 2-product:
//   S = (Qhi+Qlo) K^T  (K single fp16);  O = (Phi+Plo) V  (V single fp16)
// ---------------------------------------------------------------------------
#define AP 144                    // smem pitch bytes (64 halves + 8 pad)
#define AKV0 (2 * 128 * AP)       // Q hi+lo: 36864
#define AKV_STAGE (2 * 64 * AP)   // K, Vt slabs: 18432
#define ATT_SMEM (AKV0 + 2 * AKV_STAGE)   // 73728

__global__ __launch_bounds__(256) void attn_tc_kernel() {
    extern __shared__ __align__(256) char smem[];
    const uint32_t sbase = smem_u32(smem);
    const int tid = threadIdx.x;
    const int lane = tid & 31;
    const int warp = tid >> 5;
    const int bh = blockIdx.x;
    const int b = bh >> 5;
    const int h = bh & 31;
    const int kvh = h >> 1;
    const int qblk = (int)gridDim.y - 1 - (int)blockIdx.y;
    const int q0 = qblk * 128;
    const int wrow = warp * 16;
    const float slope = exp2f(-0.25f * (float)(h + 1));
    const float NINF = -__int_as_float(0x7f800000);

    const __half* Qhi_g = g_Qhi + ((size_t)(b * 32 + h) * 1024 + q0) * 64;
    const __half* Qlo_g = g_Qlo + ((size_t)(b * 32 + h) * 1024 + q0) * 64;
    const __half* K_g = g_K + (size_t)(b * 16 + kvh) * 1024 * 64;
    const __half* Vt_g = g_Vt + (size_t)(b * 16 + kvh) * 64 * 1024;

#pragma unroll
    for (int u = 0; u < 8; u++) {
        int idx = tid + u * 256;
        int slab = idx >> 10;
        int rem = idx & 1023;
        int row = rem >> 3, seg = rem & 7;
        const __half* src = (slab ? Qlo_g : Qhi_g) + (size_t)row * 64 + seg * 8;
        cp16(sbase + slab * (128 * AP) + row * AP + seg * 16, src);
    }
    CP_COMMIT();

    auto load_kv = [&](int t) {
        const int kv0 = t * 64;
        const uint32_t stg = sbase + AKV0 + (t & 1) * AKV_STAGE;
#pragma unroll
        for (int u = 0; u < 4; u++) {
            int idx = tid + u * 256;
            int slab = idx >> 9;            // 0: K, 1: Vt
            int rem = idx & 511;
            int row = rem >> 3, seg = rem & 7;
            const __half* src = slab ? (Vt_g + (size_t)row * 1024 + kv0 + seg * 8)
                                     : (K_g + (size_t)(kv0 + row) * 64 + seg * 8);
            cp16(stg + slab * (64 * AP) + row * AP + seg * 16, src);
        }
        CP_COMMIT();
    };

    const int nt = 2 * (qblk + 1);
    load_kv(0);
    load_kv(1);

    const int r = lane >> 2;
    const int tq = lane & 3;
    const int qq0 = q0 + wrow + r;
    const int qq1 = qq0 + 8;
    const uint32_t qrow_hi = sbase + (wrow + r) * AP + tq * 4;
    const uint32_t qrow_lo = qrow_hi + 128 * AP;

    float m0 = NINF, m1 = NINF, l0 = 0.f, l1 = 0.f;
    float oa[8][4];
#pragma unroll
    for (int nd = 0; nd < 8; nd++)
#pragma unroll
        for (int j = 0; j < 4; j++) oa[nd][j] = 0.f;

    for (int t = 0; t < nt; t++) {
        CP_WAIT1();
        __syncthreads();
        const int kv0 = t * 64;
        if (kv0 <= q0 + wrow + 15) {
            const uint32_t stg = sbase + AKV0 + (t & 1) * AKV_STAGE;
            const uint32_t vbase = stg + 64 * AP;
            // --- S = Q K^T (2-product) ---
            float sa[8][4];
#pragma unroll
            for (int nj = 0; nj < 8; nj++)
#pragma unroll
                for (int j = 0; j < 4; j++) sa[nj][j] = 0.f;
#pragma unroll
            for (int ks = 0; ks < 4; ks++) {
                const uint32_t colb = ks * 32;
                uint32_t qh[4], ql[4], kk[8][2];
                qh[0] = lds32(qrow_hi + colb);
                qh[1] = lds32(qrow_hi + 8 * AP + colb);
                qh[2] = lds32(qrow_hi + colb + 16);
                qh[3] = lds32(qrow_hi + 8 * AP + colb + 16);
                ql[0] = lds32(qrow_lo + colb);
                ql[1] = lds32(qrow_lo + 8 * AP + colb);
                ql[2] = lds32(qrow_lo + colb + 16);
                ql[3] = lds32(qrow_lo + 8 * AP + colb + 16);
#pragma unroll
                for (int nj = 0; nj < 8; nj++) {
                    uint32_t ka = stg + (nj * 8 + r) * AP + colb + tq * 4;
                    kk[nj][0] = lds32(ka);
                    kk[nj][1] = lds32(ka + 16);
                }
#pragma unroll
                for (int nj = 0; nj < 8; nj++) mma_f16(sa[nj], qh, kk[nj]);
#pragma unroll
                for (int nj = 0; nj < 8; nj++) mma_f16(sa[nj], ql, kk[nj]);
            }
            // --- softmax (online) ---
            float mloc0 = NINF, mloc1 = NINF;
#pragma unroll
            for (int nj = 0; nj < 8; nj++) {
                int c0 = kv0 + nj * 8 + 2 * tq;
                int c1 = c0 + 1;
                sa[nj][0] = (c0 <= qq0) ? sa[nj][0] * 0.125f + slope * (float)(c0 - qq0) : NINF;
                sa[nj][1] = (c1 <= qq0) ? sa[nj][1] * 0.125f + slope * (float)(c1 - qq0) : NINF;
                sa[nj][2] = (c0 <= qq1) ? sa[nj][2] * 0.125f + slope * (float)(c0 - qq1) : NINF;
                sa[nj][3] = (c1 <= qq1) ? sa[nj][3] * 0.125f + slope * (float)(c1 - qq1) : NINF;
                mloc0 = fmaxf(mloc0, fmaxf(sa[nj][0], sa[nj][1]));
                mloc1 = fmaxf(mloc1, fmaxf(sa[nj][2], sa[nj][3]));
            }
            mloc0 = fmaxf(mloc0, __shfl_xor_sync(0xffffffffu, mloc0, 1));
            mloc0 = fmaxf(mloc0, __shfl_xor_sync(0xffffffffu, mloc0, 2));
            mloc1 = fmaxf(mloc1, __shfl_xor_sync(0xffffffffu, mloc1, 1));
            mloc1 = fmaxf(mloc1, __shfl_xor_sync(0xffffffffu, mloc1, 2));
            float mn0 = fmaxf(m0, mloc0), mn1 = fmaxf(m1, mloc1);
            float corr0 = __expf(m0 - mn0), corr1 = __expf(m1 - mn1);
            m0 = mn0;
            m1 = mn1;
            float rs0 = 0.f, rs1 = 0.f;
            uint32_t ph[8][2], pl[8][2];
#pragma unroll
            for (int nj = 0; nj < 8; nj++) {
                float p00 = __expf(sa[nj][0] - mn0);
                float p01 = __expf(sa[nj][1] - mn0);
                float p10 = __expf(sa[nj][2] - mn1);
                float p11 = __expf(sa[nj][3] - mn1);
                rs0 += p00 + p01;
                rs1 += p10 + p11;
                split_pair(p00, p01, ph[nj][0], pl[nj][0]);
                split_pair(p10, p11, ph[nj][1], pl[nj][1]);
            }
            rs0 += __shfl_xor_sync(0xffffffffu, rs0, 1);
            rs0 += __shfl_xor_sync(0xffffffffu, rs0, 2);
            rs1 += __shfl_xor_sync(0xffffffffu, rs1, 1);
            rs1 += __shfl_xor_sync(0xffffffffu, rs1, 2);
            l0 = l0 * corr0 + rs0;
            l1 = l1 * corr1 + rs1;
#pragma unroll
            for (int nd = 0; nd < 8; nd++) {
                oa[nd][0] *= corr0;
                oa[nd][1] *= corr0;
                oa[nd][2] *= corr1;
                oa[nd][3] *= corr1;
            }
            // --- O += P V (2-product) ---
#pragma unroll
            for (int ks = 0; ks < 4; ks++) {
                uint32_t ah[4] = {ph[2 * ks][0], ph[2 * ks][1], ph[2 * ks + 1][0], ph[2 * ks + 1][1]};
                uint32_t al[4] = {pl[2 * ks][0], pl[2 * ks][1], pl[2 * ks + 1][0], pl[2 * ks + 1][1]};
                uint32_t vv[8][2];
#pragma unroll
                for (int nd = 0; nd < 8; nd++) {
                    uint32_t va = vbase + (nd * 8 + r) * AP + ks * 32 + tq * 4;
                    vv[nd][0] = lds32(va);
                    vv[nd][1] = lds32(va + 16);
                }
#pragma unroll
                for (int nd = 0; nd < 8; nd++) mma_f16(oa[nd], ah, vv[nd]);
#pragma unroll
                for (int nd = 0; nd < 8; nd++) mma_f16(oa[nd], al, vv[nd]);
            }
        }
        __syncthreads();
        if (t + 2 < nt) load_kv(t + 2); else CP_COMMIT();
    }

    // Epilogue: normalize, split fp16 hi/lo, store
    const float inv0 = 1.f / l0, inv1 = 1.f / l1;
    const size_t row0 = (size_t)(b * 1024 + q0 + wrow + r) * 2048 + h * 64;
    const size_t row1 = row0 + (size_t)8 * 2048;
#pragma unroll
    for (int nd = 0; nd < 8; nd++) {
        int d0 = nd * 8 + 2 * tq;
        uint32_t hh, ll;
        split_pair(oa[nd][0] * inv0, oa[nd][1] * inv0, hh, ll);
        *(uint32_t*)&g_At2hi[row0 + d0] = hh;
        *(uint32_t*)&g_At2lo[row0 + d0] = ll;
        split_pair(oa[nd][2] * inv1, oa[nd][3] * inv1, hh, ll);
        *(uint32_t*)&g_At2hi[row1 + d0] = hh;
        *(uint32_t*)&g_At2lo[row1 + d0] = ll;
    }
}

// ---------------------------------------------------------------------------
extern "C" void kernel_launch(void* const* d_in, const int* in_sizes, int n_in,
                              void* d_out, int out_size) {
    const float* inputs = (const float*)d_in[0];  // [4,1024,1024]
    const float* W_qkv  = (const float*)d_in[1];  // [1024,4096]
    const float* W_out  = (const float*)d_in[2];  // [2048,1024]
    float* out = (float*)d_out;                   // [4,1024,1024]

    cudaFuncSetAttribute(gemm_tc_kernel, cudaFuncAttributeMaxDynamicSharedMemorySize,
                         GSM_TOTAL);
    cudaFuncSetAttribute(attn_tc_kernel, cudaFuncAttributeMaxDynamicSharedMemorySize,
                         ATT_SMEM);

    __half *Ahi, *Alo, *Wq, *A2hi, *A2lo, *Wo;
    float* qkv;
    cudaGetSymbolAddress((void**)&Ahi, g_Ahi);
    cudaGetSymbolAddress((void**)&Alo, g_Alo);
    cudaGetSymbolAddress((void**)&Wq, g_Wqkv);
    cudaGetSymbolAddress((void**)&A2hi, g_At2hi);
    cudaGetSymbolAddress((void**)&A2lo, g_At2lo);
    cudaGetSymbolAddress((void**)&Wo, g_Wout);
    cudaGetSymbolAddress((void**)&qkv, g_qkv);

    // 1) split inputs; transpose both weight matrices to single fp16 [N,K]
    split_kernel<<<(ROWS * HIDDEN / 4 + 255) / 256, 256>>>(inputs, Ahi, Alo,
                                                           ROWS * HIDDEN / 4);
    transpose_h_kernel<<<dim3(QKV_COLS / 32, HIDDEN / 32), dim3(32, 8)>>>(
        W_qkv, Wq, HIDDEN, QKV_COLS);
    transpose_h_kernel<<<dim3(HIDDEN / 32, ATTN_COLS / 32), dim3(32, 8)>>>(
        W_out, Wo, ATTN_COLS, HIDDEN);

    // 2) QKV projection (2-product) -> g_qkv fp32
    gemm_tc_kernel<<<dim3(QKV_COLS / 128, ROWS / 128), 256, GSM_TOTAL>>>(
        Ahi, Alo, Wq, qkv, QKV_COLS, HIDDEN);

    // 3) prep attention operands
    prep_q_kernel<<<(BATCH * 32 * SEQL * 64 / 4) / 256, 256>>>();
    prep_k_kernel<<<(BATCH * 16 * SEQL * 64 / 4) / 256, 256>>>();
    prep_vt_kernel<<<dim3(SEQL / 64, BATCH * 16), 256>>>();

    // 4) tensor-core attention (2-product) -> g_At2hi/lo
    attn_tc_kernel<<<dim3(BATCH * 32, SEQL / 128), 256, ATT_SMEM>>>();

    // 5) Output projection (2-product) -> out
    gemm_tc_kernel<<<dim3(HIDDEN / 128, ROWS / 128), 256, GSM_TOTAL>>>(
        A2hi, A2lo, Wo, out, HIDDEN, ATTN_COLS);
}

// round 8
// speedup vs baseline: 2.0305x; 1.2507x over previous
#include <cuda_runtime.h>
#include <cuda_fp16.h>
#include <cstdint>

// Problem constants
#define BATCH 4
#define SEQL 1024
#define HIDDEN 1024
#define QKV_COLS 4096   // 2048 q + 1024 k + 1024 v
#define ATTN_COLS 2048  // 32*64
#define ROWS 4096       // BATCH*SEQL

// ---------------------------------------------------------------------------
// Scratch (__device__ globals; allocation-free rule)
// ---------------------------------------------------------------------------
__device__ float g_qkv[(size_t)ROWS * QKV_COLS];    // fp32 (V region used)
__device__ __half g_Ahi[(size_t)ROWS * HIDDEN];
__device__ __half g_Alo[(size_t)ROWS * HIDDEN];
__device__ __half g_Wqkv[(size_t)QKV_COLS * HIDDEN];   // [N,K] single fp16
__device__ __half g_At2[(size_t)ROWS * ATTN_COLS];     // attn out single fp16
__device__ __half g_Wout[(size_t)HIDDEN * ATTN_COLS];  // [N,K] single fp16
// attention operands (all single fp16)
__device__ __half g_Q[(size_t)BATCH * 32 * SEQL * 64];   // [b,h,s,d]
__device__ __half g_K[(size_t)BATCH * 16 * SEQL * 64];   // [b,kvh,s,d]
__device__ __half g_Vt[(size_t)BATCH * 16 * 64 * SEQL];  // [b,kvh,d,s]

// ---------------------------------------------------------------------------
// PTX helpers (sm_80+ only — NO tcgen05; harness targets compute_103)
// ---------------------------------------------------------------------------
__device__ __forceinline__ uint32_t smem_u32(const void* p) {
    uint32_t a;
    asm("{ .reg .u64 t; cvta.to.shared.u64 t, %1; cvt.u32.u64 %0, t; }" : "=r"(a) : "l"(p));
    return a;
}
__device__ __forceinline__ void cp16(uint32_t dst, const void* src) {
    asm volatile("cp.async.cg.shared.global [%0], [%1], 16;" :: "r"(dst), "l"(src));
}
#define CP_COMMIT() asm volatile("cp.async.commit_group;" ::: "memory")
#define CP_WAIT1()  asm volatile("cp.async.wait_group 1;" ::: "memory")

__device__ __forceinline__ uint32_t lds32(uint32_t a) {
    uint32_t v;
    asm volatile("ld.shared.b32 %0, [%1];" : "=r"(v) : "r"(a));
    return v;
}
// mma.sync m16n8k16 row.col fp16 -> fp32 accumulate
__device__ __forceinline__ void mma_f16(float* d, const uint32_t* a, const uint32_t* b) {
    asm volatile(
        "mma.sync.aligned.m16n8k16.row.col.f32.f16.f16.f32 "
        "{%0,%1,%2,%3}, {%4,%5,%6,%7}, {%8,%9}, {%0,%1,%2,%3};"
        : "+f"(d[0]), "+f"(d[1]), "+f"(d[2]), "+f"(d[3])
        : "r"(a[0]), "r"(a[1]), "r"(a[2]), "r"(a[3]), "r"(b[0]), "r"(b[1]));
}
__device__ __forceinline__ uint32_t cvt_f16x2(float f0, float f1) {
    uint32_t r;
    asm("cvt.rn.f16x2.f32 %0, %1, %2;" : "=r"(r) : "f"(f1), "f"(f0));
    return r;
}
// split a float pair into hi/lo packed fp16x2
__device__ __forceinline__ void split_pair(float f0, float f1, uint32_t& hi, uint32_t& lo) {
    hi = cvt_f16x2(f0, f1);
    __half2 h2 = *reinterpret_cast<__half2*>(&hi);
    lo = cvt_f16x2(f0 - __low2float(h2), f1 - __high2float(h2));
}

// ---------------------------------------------------------------------------
// Shared tiling constants
// ---------------------------------------------------------------------------
#define RS2 80                     // bytes per smem row (32 halves + 8 pad)
#define SLAB (128 * RS2)           // 10240 B per matrix slab

// ---------------------------------------------------------------------------
// QKV GEMM (2-product A hi/lo, single fp16 W), fused epilogue:
//   cols [0,2048)   -> g_Q  fp16 [b,h,s,d]
//   cols [2048,3072)-> g_K  fp16 [b,kvh,s,d]
//   cols [3072,4096)-> g_qkv fp32 (V, for transpose pass)
// ---------------------------------------------------------------------------
#define STAGE2 (3 * SLAB)          // Ahi, Alo, B
#define GSM2 (2 * STAGE2)          // 61440 B

__global__ __launch_bounds__(256)
void qkv_gemm_kernel(const __half* __restrict__ Ahi,
                     const __half* __restrict__ Alo,
                     const __half* __restrict__ B) {
    extern __shared__ __align__(256) char smem[];
    const uint32_t sbase = smem_u32(smem);
    const int tid = threadIdx.x;
    const int lane = tid & 31;
    const int warp = tid >> 5;
    const int wm = warp & 1;
    const int wn = warp >> 1;
    const int brow = blockIdx.y * 128;
    const int bcol = blockIdx.x * 128;
    const int Kdim = HIDDEN;

    const __half* mats[3] = {Ahi, Alo, B};
    const int KT = Kdim >> 5;

    auto load_stage = [&](int t) {
        const int s = t & 1;
        const int k0 = t << 5;
        const uint32_t stg = sbase + s * STAGE2;
#pragma unroll
        for (int m = 0; m < 3; m++) {
            const int rowbase = (m < 2) ? brow : bcol;
            const __half* base = mats[m];
#pragma unroll
            for (int u = 0; u < 2; u++) {
                int idx = tid + u * 256;
                int row = idx >> 2;
                int seg = idx & 3;
                const __half* src = base + (size_t)(rowbase + row) * Kdim + k0 + seg * 8;
                cp16(stg + m * SLAB + row * RS2 + seg * 16, src);
            }
        }
        CP_COMMIT();
    };

    float acc[4][4][4];
#pragma unroll
    for (int i = 0; i < 4; i++)
#pragma unroll
        for (int j = 0; j < 4; j++)
#pragma unroll
            for (int r = 0; r < 4; r++) acc[i][j][r] = 0.f;

    load_stage(0);
    load_stage(1);

    const int r0 = lane >> 2;
    const int cpair = (lane & 3) * 2;

    for (int t = 0; t < KT; t++) {
        CP_WAIT1();
        __syncthreads();
        const uint32_t stg = sbase + (t & 1) * STAGE2;
        const uint32_t aHi = stg + (wm * 64) * RS2;
        const uint32_t bB = stg + 2 * SLAB + (wn * 32) * RS2;

#pragma unroll
        for (int ks = 0; ks < 2; ks++) {
            const uint32_t colb = ks * 32 + cpair * 2;
            uint32_t ahi[4][4], alo[4][4], bb[4][2];
#pragma unroll
            for (int mi = 0; mi < 4; mi++) {
                uint32_t rb = (mi * 16 + r0) * RS2;
                ahi[mi][0] = lds32(aHi + rb + colb);
                ahi[mi][1] = lds32(aHi + rb + 8 * RS2 + colb);
                ahi[mi][2] = lds32(aHi + rb + colb + 16);
                ahi[mi][3] = lds32(aHi + rb + 8 * RS2 + colb + 16);
                alo[mi][0] = lds32(aHi + SLAB + rb + colb);
                alo[mi][1] = lds32(aHi + SLAB + rb + 8 * RS2 + colb);
                alo[mi][2] = lds32(aHi + SLAB + rb + colb + 16);
                alo[mi][3] = lds32(aHi + SLAB + rb + 8 * RS2 + colb + 16);
            }
#pragma unroll
            for (int nj = 0; nj < 4; nj++) {
                uint32_t rb = (nj * 8 + r0) * RS2;
                bb[nj][0] = lds32(bB + rb + colb);
                bb[nj][1] = lds32(bB + rb + colb + 16);
            }
#pragma unroll
            for (int mi = 0; mi < 4; mi++)
#pragma unroll
                for (int nj = 0; nj < 4; nj++)
                    mma_f16(acc[mi][nj], ahi[mi], bb[nj]);
#pragma unroll
            for (int mi = 0; mi < 4; mi++)
#pragma unroll
                for (int nj = 0; nj < 4; nj++)
                    mma_f16(acc[mi][nj], alo[mi], bb[nj]);
        }
        __syncthreads();
        if (t + 2 < KT) load_stage(t + 2); else CP_COMMIT();
    }

    // ---- fused epilogue ----
    if (bcol >= 3072) {
        // V region: fp32 to g_qkv
#pragma unroll
        for (int mi = 0; mi < 4; mi++) {
            int row = brow + wm * 64 + mi * 16 + r0;
#pragma unroll
            for (int nj = 0; nj < 4; nj++) {
                int col = bcol + wn * 32 + nj * 8 + cpair;
                *(float2*)(g_qkv + (size_t)row * QKV_COLS + col) =
                    make_float2(acc[mi][nj][0], acc[mi][nj][1]);
                *(float2*)(g_qkv + (size_t)(row + 8) * QKV_COLS + col) =
                    make_float2(acc[mi][nj][2], acc[mi][nj][3]);
            }
        }
    } else {
        const int b = brow >> 10;
        const bool isQ = (bcol < 2048);
        __half* dst = isQ ? g_Q : g_K;
        const int hbase = isQ ? (b * 32) : (b * 16);
        const int cadj = isQ ? 0 : 2048;
#pragma unroll
        for (int mi = 0; mi < 4; mi++) {
            int row = brow + wm * 64 + mi * 16 + r0;
            int s = row & 1023;
#pragma unroll
            for (int nj = 0; nj < 4; nj++) {
                int col = bcol - cadj + wn * 32 + nj * 8 + cpair;
                int hh = col >> 6, d = col & 63;
                size_t o0 = ((size_t)(hbase + hh) * 1024 + s) * 64 + d;
                *(uint32_t*)&dst[o0] = cvt_f16x2(acc[mi][nj][0], acc[mi][nj][1]);
                *(uint32_t*)&dst[o0 + 8 * 64] = cvt_f16x2(acc[mi][nj][2], acc[mi][nj][3]);
            }
        }
    }
}

// ---------------------------------------------------------------------------
// Out-proj GEMM (single product): C[M,N] = A[M,K](fp16) * B[N,K]^T(fp16)
// ---------------------------------------------------------------------------
#define STAGE1 (2 * SLAB)          // A, B
#define GSM1 (2 * STAGE1)          // 40960 B

__global__ __launch_bounds__(256)
void out_gemm_kernel(const __half* __restrict__ A,
                     const __half* __restrict__ B,
                     float* __restrict__ C, int Ndim, int Kdim) {
    extern __shared__ __align__(256) char smem[];
    const uint32_t sbase = smem_u32(smem);
    const int tid = threadIdx.x;
    const int lane = tid & 31;
    const int warp = tid >> 5;
    const int wm = warp & 1;
    const int wn = warp >> 1;
    const int brow = blockIdx.y * 128;
    const int bcol = blockIdx.x * 128;

    const __half* mats[2] = {A, B};
    const int KT = Kdim >> 5;

    auto load_stage = [&](int t) {
        const int s = t & 1;
        const int k0 = t << 5;
        const uint32_t stg = sbase + s * STAGE1;
#pragma unroll
        for (int m = 0; m < 2; m++) {
            const int rowbase = (m < 1) ? brow : bcol;
            const __half* base = mats[m];
#pragma unroll
            for (int u = 0; u < 2; u++) {
                int idx = tid + u * 256;
                int row = idx >> 2;
                int seg = idx & 3;
                const __half* src = base + (size_t)(rowbase + row) * Kdim + k0 + seg * 8;
                cp16(stg + m * SLAB + row * RS2 + seg * 16, src);
            }
        }
        CP_COMMIT();
    };

    float acc[4][4][4];
#pragma unroll
    for (int i = 0; i < 4; i++)
#pragma unroll
        for (int j = 0; j < 4; j++)
#pragma unroll
            for (int r = 0; r < 4; r++) acc[i][j][r] = 0.f;

    load_stage(0);
    load_stage(1);

    const int r0 = lane >> 2;
    const int cpair = (lane & 3) * 2;

    for (int t = 0; t < KT; t++) {
        CP_WAIT1();
        __syncthreads();
        const uint32_t stg = sbase + (t & 1) * STAGE1;
        const uint32_t aA = stg + (wm * 64) * RS2;
        const uint32_t bB = stg + SLAB + (wn * 32) * RS2;

#pragma unroll
        for (int ks = 0; ks < 2; ks++) {
            const uint32_t colb = ks * 32 + cpair * 2;
            uint32_t aa[4][4], bb[4][2];
#pragma unroll
            for (int mi = 0; mi < 4; mi++) {
                uint32_t rb = (mi * 16 + r0) * RS2;
                aa[mi][0] = lds32(aA + rb + colb);
                aa[mi][1] = lds32(aA + rb + 8 * RS2 + colb);
                aa[mi][2] = lds32(aA + rb + colb + 16);
                aa[mi][3] = lds32(aA + rb + 8 * RS2 + colb + 16);
            }
#pragma unroll
            for (int nj = 0; nj < 4; nj++) {
                uint32_t rb = (nj * 8 + r0) * RS2;
                bb[nj][0] = lds32(bB + rb + colb);
                bb[nj][1] = lds32(bB + rb + colb + 16);
            }
#pragma unroll
            for (int mi = 0; mi < 4; mi++)
#pragma unroll
                for (int nj = 0; nj < 4; nj++)
                    mma_f16(acc[mi][nj], aa[mi], bb[nj]);
        }
        __syncthreads();
        if (t + 2 < KT) load_stage(t + 2); else CP_COMMIT();
    }

#pragma unroll
    for (int mi = 0; mi < 4; mi++) {
        int row = brow + wm * 64 + mi * 16 + r0;
#pragma unroll
        for (int nj = 0; nj < 4; nj++) {
            int col = bcol + wn * 32 + nj * 8 + cpair;
            *(float2*)(C + (size_t)row * Ndim + col) =
                make_float2(acc[mi][nj][0], acc[mi][nj][1]);
            *(float2*)(C + (size_t)(row + 8) * Ndim + col) =
                make_float2(acc[mi][nj][2], acc[mi][nj][3]);
        }
    }
}

// ---------------------------------------------------------------------------
// Merged input prep: A split (hi/lo), Wqkv transpose->fp16, Wout transpose->fp16
// grid: [0,4096) splitA, [4096,8192) Wqkv, [8192,10240) Wout
// ---------------------------------------------------------------------------
__global__ __launch_bounds__(256) void prep_in_kernel(
    const float* __restrict__ inputs, const float* __restrict__ W_qkv,
    const float* __restrict__ W_out) {
    __shared__ float t[32][33];
    const int blk = blockIdx.x;
    const int tid = threadIdx.x;
    if (blk < 4096) {
        int i = blk * 256 + tid;
        float4 v = ((const float4*)inputs)[i];
        uint32_t h0, l0, h1, l1;
        split_pair(v.x, v.y, h0, l0);
        split_pair(v.z, v.w, h1, l1);
        ((uint2*)g_Ahi)[i] = make_uint2(h0, h1);
        ((uint2*)g_Alo)[i] = make_uint2(l0, l1);
    } else {
        const float* W;
        __half* Wt;
        int K, N, n0, k0;
        if (blk < 8192) {
            W = W_qkv; Wt = g_Wqkv; K = HIDDEN; N = QKV_COLS;
            int idx = blk - 4096;
            n0 = (idx & 127) * 32; k0 = (idx >> 7) * 32;
        } else {
            W = W_out; Wt = g_Wout; K = ATTN_COLS; N = HIDDEN;
            int idx = blk - 8192;
            n0 = (idx & 31) * 32; k0 = (idx >> 5) * 32;
        }
        int tx = tid & 31, ty = tid >> 5;
#pragma unroll
        for (int j = 0; j < 4; j++)
            t[ty + j * 8][tx] = W[(size_t)(k0 + ty + j * 8) * N + n0 + tx];
        __syncthreads();
#pragma unroll
        for (int j = 0; j < 4; j++)
            Wt[(size_t)(n0 + ty + j * 8) * K + k0 + tx] = __float2half_rn(t[tx][ty + j * 8]);
    }
}

// ---------------------------------------------------------------------------
// Prep: V fp32 [b,s,kvh,d] -> Vt fp16 [b,kvh,d,s]
// ---------------------------------------------------------------------------
__global__ __launch_bounds__(256) void prep_vt_kernel() {
    __shared__ float tile[64][65];
    int s0 = blockIdx.x * 64;
    int bk = blockIdx.y;               // b*16 + kvh
    int b = bk >> 4, kvh = bk & 15;
    int tid = threadIdx.x;
#pragma unroll
    for (int u = 0; u < 4; u++) {
        int lin = tid + u * 256;
        int row = lin >> 4, c4 = lin & 15;
        float4 v = *(const float4*)&g_qkv[((size_t)(b * 1024 + s0 + row)) * 4096 +
                                          3072 + kvh * 64 + c4 * 4];
        tile[row][c4 * 4 + 0] = v.x;
        tile[row][c4 * 4 + 1] = v.y;
        tile[row][c4 * 4 + 2] = v.z;
        tile[row][c4 * 4 + 3] = v.w;
    }
    __syncthreads();
#pragma unroll
    for (int u = 0; u < 4; u++) {
        int lin = tid + u * 256;
        int d = lin >> 4, c4 = lin & 15;
        uint32_t p0 = cvt_f16x2(tile[c4 * 4 + 0][d], tile[c4 * 4 + 1][d]);
        uint32_t p1 = cvt_f16x2(tile[c4 * 4 + 2][d], tile[c4 * 4 + 3][d]);
        size_t o = ((size_t)bk * 64 + d) * 1024 + s0 + c4 * 4;
        *(uint2*)&g_Vt[o] = make_uint2(p0, p1);
    }
}

// ---------------------------------------------------------------------------
// Tensor-core flash attention, all-single fp16 (1 MMA per QK / PV product).
// ---------------------------------------------------------------------------
#define AP 144                    // smem pitch bytes (64 halves + 8 pad)
#define AQ (128 * AP)             // Q slab: 18432
#define AKV_STAGE (2 * 64 * AP)   // K, Vt slabs: 18432
#define ATT_SMEM (AQ + 2 * AKV_STAGE)   // 55296

__global__ __launch_bounds__(256) void attn_tc_kernel() {
    extern __shared__ __align__(256) char smem[];
    const uint32_t sbase = smem_u32(smem);
    const int tid = threadIdx.x;
    const int lane = tid & 31;
    const int warp = tid >> 5;
    const int bh = blockIdx.x;
    const int b = bh >> 5;
    const int h = bh & 31;
    const int kvh = h >> 1;
    const int qblk = (int)gridDim.y - 1 - (int)blockIdx.y;
    const int q0 = qblk * 128;
    const int wrow = warp * 16;
    const float slope = exp2f(-0.25f * (float)(h + 1));
    const float NINF = -__int_as_float(0x7f800000);

    const __half* Q_g = g_Q + ((size_t)(b * 32 + h) * 1024 + q0) * 64;
    const __half* K_g = g_K + (size_t)(b * 16 + kvh) * 1024 * 64;
    const __half* Vt_g = g_Vt + (size_t)(b * 16 + kvh) * 64 * 1024;

    // Load Q (128x64): 1024 cp16
#pragma unroll
    for (int u = 0; u < 4; u++) {
        int idx = tid + u * 256;
        int row = idx >> 3, seg = idx & 7;
        cp16(sbase + row * AP + seg * 16, Q_g + (size_t)row * 64 + seg * 8);
    }
    CP_COMMIT();

    auto load_kv = [&](int t) {
        const int kv0 = t * 64;
        const uint32_t stg = sbase + AQ + (t & 1) * AKV_STAGE;
#pragma unroll
        for (int u = 0; u < 4; u++) {
            int idx = tid + u * 256;
            int slab = idx >> 9;            // 0: K, 1: Vt
            int rem = idx & 511;
            int row = rem >> 3, seg = rem & 7;
            const __half* src = slab ? (Vt_g + (size_t)row * 1024 + kv0 + seg * 8)
                                     : (K_g + (size_t)(kv0 + row) * 64 + seg * 8);
            cp16(stg + slab * (64 * AP) + row * AP + seg * 16, src);
        }
        CP_COMMIT();
    };

    const int nt = 2 * (qblk + 1);
    load_kv(0);
    load_kv(1);

    const int r = lane >> 2;
    const int tq = lane & 3;
    const int qq0 = q0 + wrow + r;
    const int qq1 = qq0 + 8;
    const uint32_t qrow = sbase + (wrow + r) * AP + tq * 4;

    float m0 = NINF, m1 = NINF, l0 = 0.f, l1 = 0.f;
    float oa[8][4];
#pragma unroll
    for (int nd = 0; nd < 8; nd++)
#pragma unroll
        for (int j = 0; j < 4; j++) oa[nd][j] = 0.f;

    for (int t = 0; t < nt; t++) {
        CP_WAIT1();
        __syncthreads();
        const int kv0 = t * 64;
        if (kv0 <= q0 + wrow + 15) {
            const uint32_t stg = sbase + AQ + (t & 1) * AKV_STAGE;
            const uint32_t vbase = stg + 64 * AP;
            // --- S = Q K^T (single product) ---
            float sa[8][4];
#pragma unroll
            for (int nj = 0; nj < 8; nj++)
#pragma unroll
                for (int j = 0; j < 4; j++) sa[nj][j] = 0.f;
#pragma unroll
            for (int ks = 0; ks < 4; ks++) {
                const uint32_t colb = ks * 32;
                uint32_t qh[4], kk[8][2];
                qh[0] = lds32(qrow + colb);
                qh[1] = lds32(qrow + 8 * AP + colb);
                qh[2] = lds32(qrow + colb + 16);
                qh[3] = lds32(qrow + 8 * AP + colb + 16);
#pragma unroll
                for (int nj = 0; nj < 8; nj++) {
                    uint32_t ka = stg + (nj * 8 + r) * AP + colb + tq * 4;
                    kk[nj][0] = lds32(ka);
                    kk[nj][1] = lds32(ka + 16);
                }
#pragma unroll
                for (int nj = 0; nj < 8; nj++) mma_f16(sa[nj], qh, kk[nj]);
            }
            // --- softmax (online) ---
            float mloc0 = NINF, mloc1 = NINF;
#pragma unroll
            for (int nj = 0; nj < 8; nj++) {
                int c0 = kv0 + nj * 8 + 2 * tq;
                int c1 = c0 + 1;
                sa[nj][0] = (c0 <= qq0) ? sa[nj][0] * 0.125f + slope * (float)(c0 - qq0) : NINF;
                sa[nj][1] = (c1 <= qq0) ? sa[nj][1] * 0.125f + slope * (float)(c1 - qq0) : NINF;
                sa[nj][2] = (c0 <= qq1) ? sa[nj][2] * 0.125f + slope * (float)(c0 - qq1) : NINF;
                sa[nj][3] = (c1 <= qq1) ? sa[nj][3] * 0.125f + slope * (float)(c1 - qq1) : NINF;
                mloc0 = fmaxf(mloc0, fmaxf(sa[nj][0], sa[nj][1]));
                mloc1 = fmaxf(mloc1, fmaxf(sa[nj][2], sa[nj][3]));
            }
            mloc0 = fmaxf(mloc0, __shfl_xor_sync(0xffffffffu, mloc0, 1));
            mloc0 = fmaxf(mloc0, __shfl_xor_sync(0xffffffffu, mloc0, 2));
            mloc1 = fmaxf(mloc1, __shfl_xor_sync(0xffffffffu, mloc1, 1));
            mloc1 = fmaxf(mloc1, __shfl_xor_sync(0xffffffffu, mloc1, 2));
            float mn0 = fmaxf(m0, mloc0), mn1 = fmaxf(m1, mloc1);
            float corr0 = __expf(m0 - mn0), corr1 = __expf(m1 - mn1);
            m0 = mn0;
            m1 = mn1;
            float rs0 = 0.f, rs1 = 0.f;
            uint32_t ph[8][2];
#pragma unroll
            for (int nj = 0; nj < 8; nj++) {
                float p00 = __expf(sa[nj][0] - mn0);
                float p01 = __expf(sa[nj][1] - mn0);
                float p10 = __expf(sa[nj][2] - mn1);
                float p11 = __expf(sa[nj][3] - mn1);
                rs0 += p00 + p01;
                rs1 += p10 + p11;
                ph[nj][0] = cvt_f16x2(p00, p01);
                ph[nj][1] = cvt_f16x2(p10, p11);
            }
            rs0 += __shfl_xor_sync(0xffffffffu, rs0, 1);
            rs0 += __shfl_xor_sync(0xffffffffu, rs0, 2);
            rs1 += __shfl_xor_sync(0xffffffffu, rs1, 1);
            rs1 += __shfl_xor_sync(0xffffffffu, rs1, 2);
            l0 = l0 * corr0 + rs0;
            l1 = l1 * corr1 + rs1;
#pragma unroll
            for (int nd = 0; nd < 8; nd++) {
                oa[nd][0] *= corr0;
                oa[nd][1] *= corr0;
                oa[nd][2] *= corr1;
                oa[nd][3] *= corr1;
            }
            // --- O += P V (single product) ---
#pragma unroll
            for (int ks = 0; ks < 4; ks++) {
                uint32_t ah[4] = {ph[2 * ks][0], ph[2 * ks][1], ph[2 * ks + 1][0], ph[2 * ks + 1][1]};
                uint32_t vv[8][2];
#pragma unroll
                for (int nd = 0; nd < 8; nd++) {
                    uint32_t va = vbase + (nd * 8 + r) * AP + ks * 32 + tq * 4;
                    vv[nd][0] = lds32(va);
                    vv[nd][1] = lds32(va + 16);
                }
#pragma unroll
                for (int nd = 0; nd < 8; nd++) mma_f16(oa[nd], ah, vv[nd]);
            }
        }
        __syncthreads();
        if (t + 2 < nt) load_kv(t + 2); else CP_COMMIT();
    }

    // Epilogue: normalize, store single fp16
    const float inv0 = 1.f / l0, inv1 = 1.f / l1;
    const size_t row0 = (size_t)(b * 1024 + q0 + wrow + r) * 2048 + h * 64;
    const size_t row1 = row0 + (size_t)8 * 2048;
#pragma unroll
    for (int nd = 0; nd < 8; nd++) {
        int d0 = nd * 8 + 2 * tq;
        *(uint32_t*)&g_At2[row0 + d0] = cvt_f16x2(oa[nd][0] * inv0, oa[nd][1] * inv0);
        *(uint32_t*)&g_At2[row1 + d0] = cvt_f16x2(oa[nd][2] * inv1, oa[nd][3] * inv1);
    }
}

// ---------------------------------------------------------------------------
extern "C" void kernel_launch(void* const* d_in, const int* in_sizes, int n_in,
                              void* d_out, int out_size) {
    const float* inputs = (const float*)d_in[0];  // [4,1024,1024]
    const float* W_qkv  = (const float*)d_in[1];  // [1024,4096]
    const float* W_out  = (const float*)d_in[2];  // [2048,1024]
    float* out = (float*)d_out;                   // [4,1024,1024]

    cudaFuncSetAttribute(qkv_gemm_kernel, cudaFuncAttributeMaxDynamicSharedMemorySize,
                         GSM2);
    cudaFuncSetAttribute(out_gemm_kernel, cudaFuncAttributeMaxDynamicSharedMemorySize,
                         GSM1);
    cudaFuncSetAttribute(attn_tc_kernel, cudaFuncAttributeMaxDynamicSharedMemorySize,
                         ATT_SMEM);

    __half *Ahi, *Alo, *Wq, *A2, *Wo;
    cudaGetSymbolAddress((void**)&Ahi, g_Ahi);
    cudaGetSymbolAddress((void**)&Alo, g_Alo);
    cudaGetSymbolAddress((void**)&Wq, g_Wqkv);
    cudaGetSymbolAddress((void**)&A2, g_At2);
    cudaGetSymbolAddress((void**)&Wo, g_Wout);

    // 1) merged input prep: A hi/lo split + both weight transposes
    prep_in_kernel<<<10240, 256>>>(inputs, W_qkv, W_out);

    // 2) QKV projection (2-product), fused epilogue -> g_Q, g_K fp16; V fp32
    qkv_gemm_kernel<<<dim3(QKV_COLS / 128, ROWS / 128), 256, GSM2>>>(Ahi, Alo, Wq);

    // 3) V transpose -> g_Vt fp16
    prep_vt_kernel<<<dim3(SEQL / 64, BATCH * 16), 256>>>();

    // 4) tensor-core attention (single product) -> g_At2 fp16
    attn_tc_kernel<<<dim3(BATCH * 32, SEQL / 128), 256, ATT_SMEM>>>();

    // 5) Output projection (single product) -> out
    out_gemm_kernel<<<dim3(HIDDEN / 128, ROWS / 128), 256, GSM1>>>(
        A2, Wo, out, HIDDEN, ATTN_COLS);
}

// round 9
// speedup vs baseline: 2.4670x; 1.2149x over previous
#include <cuda_runtime.h>
#include <cuda_fp16.h>
#include <cstdint>

// Problem constants
#define BATCH 4
#define SEQL 1024
#define HIDDEN 1024
#define QKV_COLS 4096   // 2048 q + 1024 k + 1024 v
#define ATTN_COLS 2048  // 32*64
#define ROWS 4096       // BATCH*SEQL

// ---------------------------------------------------------------------------
// Scratch (__device__ globals; allocation-free rule). All operands single fp16.
// ---------------------------------------------------------------------------
__device__ __half g_A[(size_t)ROWS * HIDDEN];          // inputs fp16
__device__ __half g_Wqkv[(size_t)QKV_COLS * HIDDEN];   // [N,K]
__device__ __half g_At2[(size_t)ROWS * ATTN_COLS];     // attn out
__device__ __half g_Wout[(size_t)HIDDEN * ATTN_COLS];  // [N,K]
__device__ __half g_Q[(size_t)BATCH * 32 * SEQL * 64];   // [b,h,s,d]
__device__ __half g_K[(size_t)BATCH * 16 * SEQL * 64];   // [b,kvh,s,d]
__device__ __half g_Vsd[(size_t)BATCH * 16 * SEQL * 64]; // [b,kvh,s,d]
__device__ __half g_Vt[(size_t)BATCH * 16 * 64 * SEQL];  // [b,kvh,d,s]

// ---------------------------------------------------------------------------
// PTX helpers (sm_80+ only — NO tcgen05; harness targets compute_103)
// ---------------------------------------------------------------------------
__device__ __forceinline__ uint32_t smem_u32(const void* p) {
    uint32_t a;
    asm("{ .reg .u64 t; cvta.to.shared.u64 t, %1; cvt.u32.u64 %0, t; }" : "=r"(a) : "l"(p));
    return a;
}
__device__ __forceinline__ void cp16(uint32_t dst, const void* src) {
    asm volatile("cp.async.cg.shared.global [%0], [%1], 16;" :: "r"(dst), "l"(src));
}
#define CP_COMMIT() asm volatile("cp.async.commit_group;" ::: "memory")
#define CP_WAIT1()  asm volatile("cp.async.wait_group 1;" ::: "memory")

__device__ __forceinline__ uint32_t lds32(uint32_t a) {
    uint32_t v;
    asm volatile("ld.shared.b32 %0, [%1];" : "=r"(v) : "r"(a));
    return v;
}
// mma.sync m16n8k16 row.col fp16 -> fp32 accumulate
__device__ __forceinline__ void mma_f16(float* d, const uint32_t* a, const uint32_t* b) {
    asm volatile(
        "mma.sync.aligned.m16n8k16.row.col.f32.f16.f16.f32 "
        "{%0,%1,%2,%3}, {%4,%5,%6,%7}, {%8,%9}, {%0,%1,%2,%3};"
        : "+f"(d[0]), "+f"(d[1]), "+f"(d[2]), "+f"(d[3])
        : "r"(a[0]), "r"(a[1]), "r"(a[2]), "r"(a[3]), "r"(b[0]), "r"(b[1]));
}
__device__ __forceinline__ uint32_t cvt_f16x2(float f0, float f1) {
    uint32_t r;
    asm("cvt.rn.f16x2.f32 %0, %1, %2;" : "=r"(r) : "f"(f1), "f"(f0));
    return r;
}

// ---------------------------------------------------------------------------
// Shared tiling constants
// ---------------------------------------------------------------------------
#define RS2 80                     // bytes per smem row (32 halves + 8 pad)
#define SLAB (128 * RS2)           // 10240 B per matrix slab
#define STAGE1 (2 * SLAB)          // A, B
#define GSM1 (2 * STAGE1)          // 40960 B

// ---------------------------------------------------------------------------
// Single-product fp16 GEMM core (shared by both GEMMs).
// mode 0: plain fp32 C store (out-proj).
// mode 1: QKV fused epilogue -> g_Q / g_K / g_Vsd fp16 head layouts.
// ---------------------------------------------------------------------------
__global__ __launch_bounds__(256)
void gemm_f16_kernel(const __half* __restrict__ A,
                     const __half* __restrict__ B,
                     float* __restrict__ C, int Ndim, int Kdim, int mode) {
    extern __shared__ __align__(256) char smem[];
    const uint32_t sbase = smem_u32(smem);
    const int tid = threadIdx.x;
    const int lane = tid & 31;
    const int warp = tid >> 5;
    const int wm = warp & 1;
    const int wn = warp >> 1;
    const int brow = blockIdx.y * 128;
    const int bcol = blockIdx.x * 128;

    const __half* mats[2] = {A, B};
    const int KT = Kdim >> 5;

    auto load_stage = [&](int t) {
        const int s = t & 1;
        const int k0 = t << 5;
        const uint32_t stg = sbase + s * STAGE1;
#pragma unroll
        for (int m = 0; m < 2; m++) {
            const int rowbase = (m < 1) ? brow : bcol;
            const __half* base = mats[m];
#pragma unroll
            for (int u = 0; u < 2; u++) {
                int idx = tid + u * 256;
                int row = idx >> 2;
                int seg = idx & 3;
                const __half* src = base + (size_t)(rowbase + row) * Kdim + k0 + seg * 8;
                cp16(stg + m * SLAB + row * RS2 + seg * 16, src);
            }
        }
        CP_COMMIT();
    };

    float acc[4][4][4];
#pragma unroll
    for (int i = 0; i < 4; i++)
#pragma unroll
        for (int j = 0; j < 4; j++)
#pragma unroll
            for (int r = 0; r < 4; r++) acc[i][j][r] = 0.f;

    load_stage(0);
    load_stage(1);

    const int r0 = lane >> 2;
    const int cpair = (lane & 3) * 2;

    for (int t = 0; t < KT; t++) {
        CP_WAIT1();
        __syncthreads();
        const uint32_t stg = sbase + (t & 1) * STAGE1;
        const uint32_t aA = stg + (wm * 64) * RS2;
        const uint32_t bB = stg + SLAB + (wn * 32) * RS2;

#pragma unroll
        for (int ks = 0; ks < 2; ks++) {
            const uint32_t colb = ks * 32 + cpair * 2;
            uint32_t aa[4][4], bb[4][2];
#pragma unroll
            for (int mi = 0; mi < 4; mi++) {
                uint32_t rb = (mi * 16 + r0) * RS2;
                aa[mi][0] = lds32(aA + rb + colb);
                aa[mi][1] = lds32(aA + rb + 8 * RS2 + colb);
                aa[mi][2] = lds32(aA + rb + colb + 16);
                aa[mi][3] = lds32(aA + rb + 8 * RS2 + colb + 16);
            }
#pragma unroll
            for (int nj = 0; nj < 4; nj++) {
                uint32_t rb = (nj * 8 + r0) * RS2;
                bb[nj][0] = lds32(bB + rb + colb);
                bb[nj][1] = lds32(bB + rb + colb + 16);
            }
#pragma unroll
            for (int mi = 0; mi < 4; mi++)
#pragma unroll
                for (int nj = 0; nj < 4; nj++)
                    mma_f16(acc[mi][nj], aa[mi], bb[nj]);
        }
        __syncthreads();
        if (t + 2 < KT) load_stage(t + 2); else CP_COMMIT();
    }

    if (mode == 0) {
#pragma unroll
        for (int mi = 0; mi < 4; mi++) {
            int row = brow + wm * 64 + mi * 16 + r0;
#pragma unroll
            for (int nj = 0; nj < 4; nj++) {
                int col = bcol + wn * 32 + nj * 8 + cpair;
                *(float2*)(C + (size_t)row * Ndim + col) =
                    make_float2(acc[mi][nj][0], acc[mi][nj][1]);
                *(float2*)(C + (size_t)(row + 8) * Ndim + col) =
                    make_float2(acc[mi][nj][2], acc[mi][nj][3]);
            }
        }
    } else {
        // fused QKV epilogue: fp16 head-layout stores
        const int b = brow >> 10;
        __half* dst;
        int hbase, cadj;
        if (bcol < 2048)       { dst = g_Q;   hbase = b * 32; cadj = 0; }
        else if (bcol < 3072)  { dst = g_K;   hbase = b * 16; cadj = 2048; }
        else                   { dst = g_Vsd; hbase = b * 16; cadj = 3072; }
#pragma unroll
        for (int mi = 0; mi < 4; mi++) {
            int row = brow + wm * 64 + mi * 16 + r0;
            int s = row & 1023;
#pragma unroll
            for (int nj = 0; nj < 4; nj++) {
                int col = bcol - cadj + wn * 32 + nj * 8 + cpair;
                int hh = col >> 6, d = col & 63;
                size_t o0 = ((size_t)(hbase + hh) * 1024 + s) * 64 + d;
                *(uint32_t*)&dst[o0] = cvt_f16x2(acc[mi][nj][0], acc[mi][nj][1]);
                *(uint32_t*)&dst[o0 + 8 * 64] = cvt_f16x2(acc[mi][nj][2], acc[mi][nj][3]);
            }
        }
    }
}

// ---------------------------------------------------------------------------
// Merged input prep: A fp32->fp16, Wqkv transpose->fp16, Wout transpose->fp16
// grid: [0,4096) A, [4096,8192) Wqkv, [8192,10240) Wout
// ---------------------------------------------------------------------------
__global__ __launch_bounds__(256) void prep_in_kernel(
    const float* __restrict__ inputs, const float* __restrict__ W_qkv,
    const float* __restrict__ W_out) {
    __shared__ float t[32][33];
    const int blk = blockIdx.x;
    const int tid = threadIdx.x;
    if (blk < 4096) {
        int i = blk * 256 + tid;
        float4 v = ((const float4*)inputs)[i];
        ((uint2*)g_A)[i] = make_uint2(cvt_f16x2(v.x, v.y), cvt_f16x2(v.z, v.w));
    } else {
        const float* W;
        __half* Wt;
        int K, N, n0, k0;
        if (blk < 8192) {
            W = W_qkv; Wt = g_Wqkv; K = HIDDEN; N = QKV_COLS;
            int idx = blk - 4096;
            n0 = (idx & 127) * 32; k0 = (idx >> 7) * 32;
        } else {
            W = W_out; Wt = g_Wout; K = ATTN_COLS; N = HIDDEN;
            int idx = blk - 8192;
            n0 = (idx & 31) * 32; k0 = (idx >> 5) * 32;
        }
        int tx = tid & 31, ty = tid >> 5;
#pragma unroll
        for (int j = 0; j < 4; j++)
            t[ty + j * 8][tx] = W[(size_t)(k0 + ty + j * 8) * N + n0 + tx];
        __syncthreads();
#pragma unroll
        for (int j = 0; j < 4; j++)
            Wt[(size_t)(n0 + ty + j * 8) * K + k0 + tx] = __float2half_rn(t[tx][ty + j * 8]);
    }
}

// ---------------------------------------------------------------------------
// Prep: V fp16 [b,kvh,s,d] -> Vt fp16 [b,kvh,d,s]
// ---------------------------------------------------------------------------
__global__ __launch_bounds__(256) void prep_vt_kernel() {
    __shared__ __half tile[64][66];
    int s0 = blockIdx.x * 64;
    int bk = blockIdx.y;               // b*16 + kvh
    int tid = threadIdx.x;
#pragma unroll
    for (int u = 0; u < 4; u++) {
        int lin = tid + u * 256;
        int row = lin >> 4, c4 = lin & 15;
        uint2 v = *(const uint2*)&g_Vsd[((size_t)bk * 1024 + s0 + row) * 64 + c4 * 4];
        *(uint32_t*)&tile[row][c4 * 4] = v.x;
        *(uint32_t*)&tile[row][c4 * 4 + 2] = v.y;
    }
    __syncthreads();
#pragma unroll
    for (int u = 0; u < 4; u++) {
        int lin = tid + u * 256;
        int d = lin >> 4, c4 = lin & 15;
        int ss = c4 * 4;
        uint32_t p0 = (uint32_t)*(const uint16_t*)&tile[ss][d] |
                      ((uint32_t)*(const uint16_t*)&tile[ss + 1][d] << 16);
        uint32_t p1 = (uint32_t)*(const uint16_t*)&tile[ss + 2][d] |
                      ((uint32_t)*(const uint16_t*)&tile[ss + 3][d] << 16);
        size_t o = ((size_t)bk * 64 + d) * 1024 + s0 + ss;
        *(uint2*)&g_Vt[o] = make_uint2(p0, p1);
    }
}

// ---------------------------------------------------------------------------
// Tensor-core flash attention, all-single fp16 (1 MMA per QK / PV product).
// Warp-uniform fast path for tiles fully below the causal diagonal.
// ---------------------------------------------------------------------------
#define AP 144                    // smem pitch bytes (64 halves + 8 pad)
#define AQ (128 * AP)             // Q slab: 18432
#define AKV_STAGE (2 * 64 * AP)   // K, Vt slabs: 18432
#define ATT_SMEM (AQ + 2 * AKV_STAGE)   // 55296

__global__ __launch_bounds__(256) void attn_tc_kernel() {
    extern __shared__ __align__(256) char smem[];
    const uint32_t sbase = smem_u32(smem);
    const int tid = threadIdx.x;
    const int lane = tid & 31;
    const int warp = tid >> 5;
    const int bh = blockIdx.x;
    const int b = bh >> 5;
    const int h = bh & 31;
    const int kvh = h >> 1;
    const int qblk = (int)gridDim.y - 1 - (int)blockIdx.y;
    const int q0 = qblk * 128;
    const int wrow = warp * 16;
    const float slope = exp2f(-0.25f * (float)(h + 1));
    const float NINF = -__int_as_float(0x7f800000);

    const __half* Q_g = g_Q + ((size_t)(b * 32 + h) * 1024 + q0) * 64;
    const __half* K_g = g_K + (size_t)(b * 16 + kvh) * 1024 * 64;
    const __half* Vt_g = g_Vt + (size_t)(b * 16 + kvh) * 64 * 1024;

    // Load Q (128x64)
#pragma unroll
    for (int u = 0; u < 4; u++) {
        int idx = tid + u * 256;
        int row = idx >> 3, seg = idx & 7;
        cp16(sbase + row * AP + seg * 16, Q_g + (size_t)row * 64 + seg * 8);
    }
    CP_COMMIT();

    auto load_kv = [&](int t) {
        const int kv0 = t * 64;
        const uint32_t stg = sbase + AQ + (t & 1) * AKV_STAGE;
#pragma unroll
        for (int u = 0; u < 4; u++) {
            int idx = tid + u * 256;
            int slab = idx >> 9;            // 0: K, 1: Vt
            int rem = idx & 511;
            int row = rem >> 3, seg = rem & 7;
            const __half* src = slab ? (Vt_g + (size_t)row * 1024 + kv0 + seg * 8)
                                     : (K_g + (size_t)(kv0 + row) * 64 + seg * 8);
            cp16(stg + slab * (64 * AP) + row * AP + seg * 16, src);
        }
        CP_COMMIT();
    };

    const int nt = 2 * (qblk + 1);
    load_kv(0);
    load_kv(1);

    const int r = lane >> 2;
    const int tq = lane & 3;
    const int qq0 = q0 + wrow + r;
    const int qq1 = qq0 + 8;
    const uint32_t qrow = sbase + (wrow + r) * AP + tq * 4;

    float m0 = NINF, m1 = NINF, l0 = 0.f, l1 = 0.f;
    float oa[8][4];
#pragma unroll
    for (int nd = 0; nd < 8; nd++)
#pragma unroll
        for (int j = 0; j < 4; j++) oa[nd][j] = 0.f;

    for (int t = 0; t < nt; t++) {
        CP_WAIT1();
        __syncthreads();
        const int kv0 = t * 64;
        if (kv0 <= q0 + wrow + 15) {
            const uint32_t stg = sbase + AQ + (t & 1) * AKV_STAGE;
            const uint32_t vbase = stg + 64 * AP;
            // --- S = Q K^T (single product) ---
            float sa[8][4];
#pragma unroll
            for (int nj = 0; nj < 8; nj++)
#pragma unroll
                for (int j = 0; j < 4; j++) sa[nj][j] = 0.f;
#pragma unroll
            for (int ks = 0; ks < 4; ks++) {
                const uint32_t colb = ks * 32;
                uint32_t qh[4], kk[8][2];
                qh[0] = lds32(qrow + colb);
                qh[1] = lds32(qrow + 8 * AP + colb);
                qh[2] = lds32(qrow + colb + 16);
                qh[3] = lds32(qrow + 8 * AP + colb + 16);
#pragma unroll
                for (int nj = 0; nj < 8; nj++) {
                    uint32_t ka = stg + (nj * 8 + r) * AP + colb + tq * 4;
                    kk[nj][0] = lds32(ka);
                    kk[nj][1] = lds32(ka + 16);
                }
#pragma unroll
                for (int nj = 0; nj < 8; nj++) mma_f16(sa[nj], qh, kk[nj]);
            }
            // --- scale + ALiBi (+ causal mask only near the diagonal) ---
            float mloc0 = NINF, mloc1 = NINF;
            if (kv0 + 63 <= q0 + wrow) {
                // warp-uniform fast path: all columns valid for all warp rows
#pragma unroll
                for (int nj = 0; nj < 8; nj++) {
                    int c0 = kv0 + nj * 8 + 2 * tq;
                    float fc0 = (float)c0, fc1 = (float)(c0 + 1);
                    sa[nj][0] = sa[nj][0] * 0.125f + slope * (fc0 - (float)qq0);
                    sa[nj][1] = sa[nj][1] * 0.125f + slope * (fc1 - (float)qq0);
                    sa[nj][2] = sa[nj][2] * 0.125f + slope * (fc0 - (float)qq1);
                    sa[nj][3] = sa[nj][3] * 0.125f + slope * (fc1 - (float)qq1);
                    mloc0 = fmaxf(mloc0, fmaxf(sa[nj][0], sa[nj][1]));
                    mloc1 = fmaxf(mloc1, fmaxf(sa[nj][2], sa[nj][3]));
                }
            } else {
#pragma unroll
                for (int nj = 0; nj < 8; nj++) {
                    int c0 = kv0 + nj * 8 + 2 * tq;
                    int c1 = c0 + 1;
                    sa[nj][0] = (c0 <= qq0) ? sa[nj][0] * 0.125f + slope * (float)(c0 - qq0) : NINF;
                    sa[nj][1] = (c1 <= qq0) ? sa[nj][1] * 0.125f + slope * (float)(c1 - qq0) : NINF;
                    sa[nj][2] = (c0 <= qq1) ? sa[nj][2] * 0.125f + slope * (float)(c0 - qq1) : NINF;
                    sa[nj][3] = (c1 <= qq1) ? sa[nj][3] * 0.125f + slope * (float)(c1 - qq1) : NINF;
                    mloc0 = fmaxf(mloc0, fmaxf(sa[nj][0], sa[nj][1]));
                    mloc1 = fmaxf(mloc1, fmaxf(sa[nj][2], sa[nj][3]));
                }
            }
            mloc0 = fmaxf(mloc0, __shfl_xor_sync(0xffffffffu, mloc0, 1));
            mloc0 = fmaxf(mloc0, __shfl_xor_sync(0xffffffffu, mloc0, 2));
            mloc1 = fmaxf(mloc1, __shfl_xor_sync(0xffffffffu, mloc1, 1));
            mloc1 = fmaxf(mloc1, __shfl_xor_sync(0xffffffffu, mloc1, 2));
            float mn0 = fmaxf(m0, mloc0), mn1 = fmaxf(m1, mloc1);
            float corr0 = __expf(m0 - mn0), corr1 = __expf(m1 - mn1);
            m0 = mn0;
            m1 = mn1;
            float rs0 = 0.f, rs1 = 0.f;
            uint32_t ph[8][2];
#pragma unroll
            for (int nj = 0; nj < 8; nj++) {
                float p00 = __expf(sa[nj][0] - mn0);
                float p01 = __expf(sa[nj][1] - mn0);
                float p10 = __expf(sa[nj][2] - mn1);
                float p11 = __expf(sa[nj][3] - mn1);
                rs0 += p00 + p01;
                rs1 += p10 + p11;
                ph[nj][0] = cvt_f16x2(p00, p01);
                ph[nj][1] = cvt_f16x2(p10, p11);
            }
            rs0 += __shfl_xor_sync(0xffffffffu, rs0, 1);
            rs0 += __shfl_xor_sync(0xffffffffu, rs0, 2);
            rs1 += __shfl_xor_sync(0xffffffffu, rs1, 1);
            rs1 += __shfl_xor_sync(0xffffffffu, rs1, 2);
            l0 = l0 * corr0 + rs0;
            l1 = l1 * corr1 + rs1;
#pragma unroll
            for (int nd = 0; nd < 8; nd++) {
                oa[nd][0] *= corr0;
                oa[nd][1] *= corr0;
                oa[nd][2] *= corr1;
                oa[nd][3] *= corr1;
            }
            // --- O += P V (single product) ---
#pragma unroll
            for (int ks = 0; ks < 4; ks++) {
                uint32_t ah[4] = {ph[2 * ks][0], ph[2 * ks][1], ph[2 * ks + 1][0], ph[2 * ks + 1][1]};
                uint32_t vv[8][2];
#pragma unroll
                for (int nd = 0; nd < 8; nd++) {
                    uint32_t va = vbase + (nd * 8 + r) * AP + ks * 32 + tq * 4;
                    vv[nd][0] = lds32(va);
                    vv[nd][1] = lds32(va + 16);
                }
#pragma unroll
                for (int nd = 0; nd < 8; nd++) mma_f16(oa[nd], ah, vv[nd]);
            }
        }
        __syncthreads();
        if (t + 2 < nt) load_kv(t + 2); else CP_COMMIT();
    }

    // Epilogue: normalize, store single fp16
    const float inv0 = 1.f / l0, inv1 = 1.f / l1;
    const size_t row0 = (size_t)(b * 1024 + q0 + wrow + r) * 2048 + h * 64;
    const size_t row1 = row0 + (size_t)8 * 2048;
#pragma unroll
    for (int nd = 0; nd < 8; nd++) {
        int d0 = nd * 8 + 2 * tq;
        *(uint32_t*)&g_At2[row0 + d0] = cvt_f16x2(oa[nd][0] * inv0, oa[nd][1] * inv0);
        *(uint32_t*)&g_At2[row1 + d0] = cvt_f16x2(oa[nd][2] * inv1, oa[nd][3] * inv1);
    }
}

// ---------------------------------------------------------------------------
extern "C" void kernel_launch(void* const* d_in, const int* in_sizes, int n_in,
                              void* d_out, int out_size) {
    const float* inputs = (const float*)d_in[0];  // [4,1024,1024]
    const float* W_qkv  = (const float*)d_in[1];  // [1024,4096]
    const float* W_out  = (const float*)d_in[2];  // [2048,1024]
    float* out = (float*)d_out;                   // [4,1024,1024]

    cudaFuncSetAttribute(gemm_f16_kernel, cudaFuncAttributeMaxDynamicSharedMemorySize,
                         GSM1);
    cudaFuncSetAttribute(attn_tc_kernel, cudaFuncAttributeMaxDynamicSharedMemorySize,
                         ATT_SMEM);

    __half *A, *Wq, *A2, *Wo;
    cudaGetSymbolAddress((void**)&A, g_A);
    cudaGetSymbolAddress((void**)&Wq, g_Wqkv);
    cudaGetSymbolAddress((void**)&A2, g_At2);
    cudaGetSymbolAddress((void**)&Wo, g_Wout);

    // 1) merged input prep: A fp16 convert + both weight transposes
    prep_in_kernel<<<10240, 256>>>(inputs, W_qkv, W_out);

    // 2) QKV projection (single product), fused epilogue -> g_Q/g_K/g_Vsd fp16
    gemm_f16_kernel<<<dim3(QKV_COLS / 128, ROWS / 128), 256, GSM1>>>(
        A, Wq, nullptr, QKV_COLS, HIDDEN, 1);

    // 3) V transpose (fp16 -> fp16) -> g_Vt
    prep_vt_kernel<<<dim3(SEQL / 64, BATCH * 16), 256>>>();

    // 4) tensor-core attention (single product) -> g_At2 fp16
    attn_tc_kernel<<<dim3(BATCH * 32, SEQL / 128), 256, ATT_SMEM>>>();

    // 5) Output projection (single product) -> out
    gemm_f16_kernel<<<dim3(HIDDEN / 128, ROWS / 128), 256, GSM1>>>(
        A2, Wo, out, HIDDEN, ATTN_COLS, 0);
}

// round 10
// speedup vs baseline: 2.5010x; 1.0138x over previous
#include <cuda_runtime.h>
#include <cuda_fp16.h>
#include <cstdint>

// Problem constants
#define BATCH 4
#define SEQL 1024
#define HIDDEN 1024
#define QKV_COLS 4096   // 2048 q + 1024 k + 1024 v
#define ATTN_COLS 2048  // 32*64
#define ROWS 4096       // BATCH*SEQL

// ---------------------------------------------------------------------------
// Scratch (__device__ globals; allocation-free rule). All operands single fp16.
// ---------------------------------------------------------------------------
__device__ __half g_A[(size_t)ROWS * HIDDEN];          // inputs fp16
__device__ __half g_Wqkv[(size_t)QKV_COLS * HIDDEN];   // [N,K]
__device__ __half g_At2[(size_t)ROWS * ATTN_COLS];     // attn out
__device__ __half g_Wout[(size_t)HIDDEN * ATTN_COLS];  // [N,K]
__device__ __half g_Q[(size_t)BATCH * 32 * SEQL * 64];   // [b,h,s,d]
__device__ __half g_K[(size_t)BATCH * 16 * SEQL * 64];   // [b,kvh,s,d]
__device__ __half g_Vt[(size_t)BATCH * 16 * 64 * SEQL];  // [b,kvh,d,s]

// ---------------------------------------------------------------------------
// PTX helpers (sm_80+ only — NO tcgen05; harness targets compute_103)
// ---------------------------------------------------------------------------
__device__ __forceinline__ uint32_t smem_u32(const void* p) {
    uint32_t a;
    asm("{ .reg .u64 t; cvta.to.shared.u64 t, %1; cvt.u32.u64 %0, t; }" : "=r"(a) : "l"(p));
    return a;
}
__device__ __forceinline__ void cp16(uint32_t dst, const void* src) {
    asm volatile("cp.async.cg.shared.global [%0], [%1], 16;" :: "r"(dst), "l"(src));
}
#define CP_COMMIT() asm volatile("cp.async.commit_group;" ::: "memory")
#define CP_WAIT1()  asm volatile("cp.async.wait_group 1;" ::: "memory")

__device__ __forceinline__ uint32_t lds32(uint32_t a) {
    uint32_t v;
    asm volatile("ld.shared.b32 %0, [%1];" : "=r"(v) : "r"(a));
    return v;
}
// mma.sync m16n8k16 row.col fp16 -> fp32 accumulate
__device__ __forceinline__ void mma_f16(float* d, const uint32_t* a, const uint32_t* b) {
    asm volatile(
        "mma.sync.aligned.m16n8k16.row.col.f32.f16.f16.f32 "
        "{%0,%1,%2,%3}, {%4,%5,%6,%7}, {%8,%9}, {%0,%1,%2,%3};"
        : "+f"(d[0]), "+f"(d[1]), "+f"(d[2]), "+f"(d[3])
        : "r"(a[0]), "r"(a[1]), "r"(a[2]), "r"(a[3]), "r"(b[0]), "r"(b[1]));
}
__device__ __forceinline__ uint32_t cvt_f16x2(float f0, float f1) {
    uint32_t r;
    asm("cvt.rn.f16x2.f32 %0, %1, %2;" : "=r"(r) : "f"(f1), "f"(f0));
    return r;
}
// raw ex2.approx (base-2 exp, single MUFU op)
__device__ __forceinline__ float ex2(float x) {
    float r;
    asm("ex2.approx.f32 %0, %1;" : "=f"(r) : "f"(x));
    return r;
}

// ---------------------------------------------------------------------------
// Shared tiling constants
// ---------------------------------------------------------------------------
#define RS2 80                     // bytes per smem row (32 halves + 8 pad)
#define SLAB (128 * RS2)           // 10240 B per matrix slab
#define STAGE1 (2 * SLAB)          // A, B
#define GSM1 (2 * STAGE1)          // 40960 B

// ---------------------------------------------------------------------------
// Single-product fp16 GEMM core.
// mode 0: plain fp32 C store (out-proj).
// mode 1: QKV fused epilogue -> g_Q / g_K fp16 head layouts; V cols are
//         transposed through smem into g_Vt [b,kvh,d,s] (coalesced stores).
// ---------------------------------------------------------------------------
__global__ __launch_bounds__(256)
void gemm_f16_kernel(const __half* __restrict__ A,
                     const __half* __restrict__ B,
                     float* __restrict__ C, int Ndim, int Kdim, int mode) {
    extern __shared__ __align__(256) char smem[];
    const uint32_t sbase = smem_u32(smem);
    const int tid = threadIdx.x;
    const int lane = tid & 31;
    const int warp = tid >> 5;
    const int wm = warp & 1;
    const int wn = warp >> 1;
    const int brow = blockIdx.y * 128;
    const int bcol = blockIdx.x * 128;

    const __half* mats[2] = {A, B};
    const int KT = Kdim >> 5;

    auto load_stage = [&](int t) {
        const int s = t & 1;
        const int k0 = t << 5;
        const uint32_t stg = sbase + s * STAGE1;
#pragma unroll
        for (int m = 0; m < 2; m++) {
            const int rowbase = (m < 1) ? brow : bcol;
            const __half* base = mats[m];
#pragma unroll
            for (int u = 0; u < 2; u++) {
                int idx = tid + u * 256;
                int row = idx >> 2;
                int seg = idx & 3;
                const __half* src = base + (size_t)(rowbase + row) * Kdim + k0 + seg * 8;
                cp16(stg + m * SLAB + row * RS2 + seg * 16, src);
            }
        }
        CP_COMMIT();
    };

    float acc[4][4][4];
#pragma unroll
    for (int i = 0; i < 4; i++)
#pragma unroll
        for (int j = 0; j < 4; j++)
#pragma unroll
            for (int r = 0; r < 4; r++) acc[i][j][r] = 0.f;

    load_stage(0);
    load_stage(1);

    const int r0 = lane >> 2;
    const int cpair = (lane & 3) * 2;

    for (int t = 0; t < KT; t++) {
        CP_WAIT1();
        __syncthreads();
        const uint32_t stg = sbase + (t & 1) * STAGE1;
        const uint32_t aA = stg + (wm * 64) * RS2;
        const uint32_t bB = stg + SLAB + (wn * 32) * RS2;

#pragma unroll
        for (int ks = 0; ks < 2; ks++) {
            const uint32_t colb = ks * 32 + cpair * 2;
            uint32_t aa[4][4], bb[4][2];
#pragma unroll
            for (int mi = 0; mi < 4; mi++) {
                uint32_t rb = (mi * 16 + r0) * RS2;
                aa[mi][0] = lds32(aA + rb + colb);
                aa[mi][1] = lds32(aA + rb + 8 * RS2 + colb);
                aa[mi][2] = lds32(aA + rb + colb + 16);
                aa[mi][3] = lds32(aA + rb + 8 * RS2 + colb + 16);
            }
#pragma unroll
            for (int nj = 0; nj < 4; nj++) {
                uint32_t rb = (nj * 8 + r0) * RS2;
                bb[nj][0] = lds32(bB + rb + colb);
                bb[nj][1] = lds32(bB + rb + colb + 16);
            }
#pragma unroll
            for (int mi = 0; mi < 4; mi++)
#pragma unroll
                for (int nj = 0; nj < 4; nj++)
                    mma_f16(acc[mi][nj], aa[mi], bb[nj]);
        }
        __syncthreads();
        if (t + 2 < KT) load_stage(t + 2); else CP_COMMIT();
    }

    if (mode == 0) {
#pragma unroll
        for (int mi = 0; mi < 4; mi++) {
            int row = brow + wm * 64 + mi * 16 + r0;
#pragma unroll
            for (int nj = 0; nj < 4; nj++) {
                int col = bcol + wn * 32 + nj * 8 + cpair;
                *(float2*)(C + (size_t)row * Ndim + col) =
                    make_float2(acc[mi][nj][0], acc[mi][nj][1]);
                *(float2*)(C + (size_t)(row + 8) * Ndim + col) =
                    make_float2(acc[mi][nj][2], acc[mi][nj][3]);
            }
        }
    } else if (bcol < 3072) {
        // Q / K fp16 head-layout stores
        const int b = brow >> 10;
        const bool isQ = (bcol < 2048);
        __half* dst = isQ ? g_Q : g_K;
        const int hbase = isQ ? (b * 32) : (b * 16);
        const int cadj = isQ ? 0 : 2048;
#pragma unroll
        for (int mi = 0; mi < 4; mi++) {
            int row = brow + wm * 64 + mi * 16 + r0;
            int s = row & 1023;
#pragma unroll
            for (int nj = 0; nj < 4; nj++) {
                int col = bcol - cadj + wn * 32 + nj * 8 + cpair;
                int hh = col >> 6, d = col & 63;
                size_t o0 = ((size_t)(hbase + hh) * 1024 + s) * 64 + d;
                *(uint32_t*)&dst[o0] = cvt_f16x2(acc[mi][nj][0], acc[mi][nj][1]);
                *(uint32_t*)&dst[o0 + 8 * 64] = cvt_f16x2(acc[mi][nj][2], acc[mi][nj][3]);
            }
        }
    } else {
        // V: stage fp16 transposed in smem, then coalesced store to g_Vt[b,kvh,d,s]
        const int b = brow >> 10;
        const int s0 = brow & 1023;
        const int vcol0 = bcol - 3072;          // 0..896
        __half* tile = (__half*)smem;           // [128 cols][136 pitch]
        const int P = 136;
#pragma unroll
        for (int mi = 0; mi < 4; mi++) {
            int r = wm * 64 + mi * 16 + r0;     // local row (s)
#pragma unroll
            for (int nj = 0; nj < 4; nj++) {
                int c = wn * 32 + nj * 8 + cpair;  // local col (v dim)
                tile[c * P + r] = __float2half_rn(acc[mi][nj][0]);
                tile[(c + 1) * P + r] = __float2half_rn(acc[mi][nj][1]);
                tile[c * P + r + 8] = __float2half_rn(acc[mi][nj][2]);
                tile[(c + 1) * P + r + 8] = __float2half_rn(acc[mi][nj][3]);
            }
        }
        __syncthreads();
        // write out: thread -> (c = tid/2, half-row hs = tid&1), 64 halves each
        int c = tid >> 1, hs = tid & 1;
        int kvh = (vcol0 + c) >> 6, d = (vcol0 + c) & 63;
        const __half* srcp = tile + c * P + hs * 64;
        size_t o = ((size_t)(b * 16 + kvh) * 64 + d) * 1024 + s0 + hs * 64;
#pragma unroll
        for (int i = 0; i < 8; i++)
            ((uint4*)&g_Vt[o])[i] = ((const uint4*)srcp)[i];
    }
}

// ---------------------------------------------------------------------------
// Merged input prep: A fp32->fp16, Wqkv transpose->fp16, Wout transpose->fp16
// grid: [0,4096) A, [4096,8192) Wqkv, [8192,10240) Wout
// ---------------------------------------------------------------------------
__global__ __launch_bounds__(256) void prep_in_kernel(
    const float* __restrict__ inputs, const float* __restrict__ W_qkv,
    const float* __restrict__ W_out) {
    __shared__ float t[32][33];
    const int blk = blockIdx.x;
    const int tid = threadIdx.x;
    if (blk < 4096) {
        int i = blk * 256 + tid;
        float4 v = ((const float4*)inputs)[i];
        ((uint2*)g_A)[i] = make_uint2(cvt_f16x2(v.x, v.y), cvt_f16x2(v.z, v.w));
    } else {
        const float* W;
        __half* Wt;
        int K, N, n0, k0;
        if (blk < 8192) {
            W = W_qkv; Wt = g_Wqkv; K = HIDDEN; N = QKV_COLS;
            int idx = blk - 4096;
            n0 = (idx & 127) * 32; k0 = (idx >> 7) * 32;
        } else {
            W = W_out; Wt = g_Wout; K = ATTN_COLS; N = HIDDEN;
            int idx = blk - 8192;
            n0 = (idx & 31) * 32; k0 = (idx >> 5) * 32;
        }
        int tx = tid & 31, ty = tid >> 5;
#pragma unroll
        for (int j = 0; j < 4; j++)
            t[ty + j * 8][tx] = W[(size_t)(k0 + ty + j * 8) * N + n0 + tx];
        __syncthreads();
#pragma unroll
        for (int j = 0; j < 4; j++)
            Wt[(size_t)(n0 + ty + j * 8) * K + k0 + tx] = __float2half_rn(t[tx][ty + j * 8]);
    }
}

// ---------------------------------------------------------------------------
// Tensor-core flash attention, single fp16, log2-domain softmax.
// ---------------------------------------------------------------------------
#define AP 144                    // smem pitch bytes (64 halves + 8 pad)
#define AQ (128 * AP)             // Q slab: 18432
#define AKV_STAGE (2 * 64 * AP)   // K, Vt slabs: 18432
#define ATT_SMEM (AQ + 2 * AKV_STAGE)   // 55296

__global__ __launch_bounds__(256) void attn_tc_kernel() {
    extern __shared__ __align__(256) char smem[];
    const uint32_t sbase = smem_u32(smem);
    const int tid = threadIdx.x;
    const int lane = tid & 31;
    const int warp = tid >> 5;
    const int bh = blockIdx.x;
    const int b = bh >> 5;
    const int h = bh & 31;
    const int kvh = h >> 1;
    const int qblk = (int)gridDim.y - 1 - (int)blockIdx.y;
    const int q0 = qblk * 128;
    const int wrow = warp * 16;
    // log2-domain constants: p = 2^(s*k1 + slope2*(c-q) - m2)
    const float k1 = 0.125f * 1.44269504f;
    const float slope2 = exp2f(-0.25f * (float)(h + 1)) * 1.44269504f;
    const float NINF = -__int_as_float(0x7f800000);

    const __half* Q_g = g_Q + ((size_t)(b * 32 + h) * 1024 + q0) * 64;
    const __half* K_g = g_K + (size_t)(b * 16 + kvh) * 1024 * 64;
    const __half* Vt_g = g_Vt + (size_t)(b * 16 + kvh) * 64 * 1024;

    // Load Q (128x64)
#pragma unroll
    for (int u = 0; u < 4; u++) {
        int idx = tid + u * 256;
        int row = idx >> 3, seg = idx & 7;
        cp16(sbase + row * AP + seg * 16, Q_g + (size_t)row * 64 + seg * 8);
    }
    CP_COMMIT();

    auto load_kv = [&](int t) {
        const int kv0 = t * 64;
        const uint32_t stg = sbase + AQ + (t & 1) * AKV_STAGE;
#pragma unroll
        for (int u = 0; u < 4; u++) {
            int idx = tid + u * 256;
            int slab = idx >> 9;            // 0: K, 1: Vt
            int rem = idx & 511;
            int row = rem >> 3, seg = rem & 7;
            const __half* src = slab ? (Vt_g + (size_t)row * 1024 + kv0 + seg * 8)
                                     : (K_g + (size_t)(kv0 + row) * 64 + seg * 8);
            cp16(stg + slab * (64 * AP) + row * AP + seg * 16, src);
        }
        CP_COMMIT();
    };

    const int nt = 2 * (qblk + 1);
    load_kv(0);
    load_kv(1);

    const int r = lane >> 2;
    const int tq = lane & 3;
    const int qq0 = q0 + wrow + r;
    const int qq1 = qq0 + 8;
    const uint32_t qrow = sbase + (wrow + r) * AP + tq * 4;

    float m0 = NINF, m1 = NINF, l0 = 0.f, l1 = 0.f;
    float oa[8][4];
#pragma unroll
    for (int nd = 0; nd < 8; nd++)
#pragma unroll
        for (int j = 0; j < 4; j++) oa[nd][j] = 0.f;

    for (int t = 0; t < nt; t++) {
        CP_WAIT1();
        __syncthreads();
        const int kv0 = t * 64;
        if (kv0 <= q0 + wrow + 15) {
            const uint32_t stg = sbase + AQ + (t & 1) * AKV_STAGE;
            const uint32_t vbase = stg + 64 * AP;
            // --- S = Q K^T ---
            float sa[8][4];
#pragma unroll
            for (int nj = 0; nj < 8; nj++)
#pragma unroll
                for (int j = 0; j < 4; j++) sa[nj][j] = 0.f;
#pragma unroll
            for (int ks = 0; ks < 4; ks++) {
                const uint32_t colb = ks * 32;
                uint32_t qh[4], kk[8][2];
                qh[0] = lds32(qrow + colb);
                qh[1] = lds32(qrow + 8 * AP + colb);
                qh[2] = lds32(qrow + colb + 16);
                qh[3] = lds32(qrow + 8 * AP + colb + 16);
#pragma unroll
                for (int nj = 0; nj < 8; nj++) {
                    uint32_t ka = stg + (nj * 8 + r) * AP + colb + tq * 4;
                    kk[nj][0] = lds32(ka);
                    kk[nj][1] = lds32(ka + 16);
                }
#pragma unroll
                for (int nj = 0; nj < 8; nj++) mma_f16(sa[nj], qh, kk[nj]);
            }
            // --- log2-domain scale + ALiBi (+ mask only near diagonal) ---
            float mloc0 = NINF, mloc1 = NINF;
            if (kv0 + 63 <= q0 + wrow) {
#pragma unroll
                for (int nj = 0; nj < 8; nj++) {
                    int c0 = kv0 + nj * 8 + 2 * tq;
                    float fc0 = (float)c0, fc1 = (float)(c0 + 1);
                    sa[nj][0] = sa[nj][0] * k1 + slope2 * (fc0 - (float)qq0);
                    sa[nj][1] = sa[nj][1] * k1 + slope2 * (fc1 - (float)qq0);
                    sa[nj][2] = sa[nj][2] * k1 + slope2 * (fc0 - (float)qq1);
                    sa[nj][3] = sa[nj][3] * k1 + slope2 * (fc1 - (float)qq1);
                    mloc0 = fmaxf(mloc0, fmaxf(sa[nj][0], sa[nj][1]));
                    mloc1 = fmaxf(mloc1, fmaxf(sa[nj][2], sa[nj][3]));
                }
            } else {
#pragma unroll
                for (int nj = 0; nj < 8; nj++) {
                    int c0 = kv0 + nj * 8 + 2 * tq;
                    int c1 = c0 + 1;
                    sa[nj][0] = (c0 <= qq0) ? sa[nj][0] * k1 + slope2 * (float)(c0 - qq0) : NINF;
                    sa[nj][1] = (c1 <= qq0) ? sa[nj][1] * k1 + slope2 * (float)(c1 - qq0) : NINF;
                    sa[nj][2] = (c0 <= qq1) ? sa[nj][2] * k1 + slope2 * (float)(c0 - qq1) : NINF;
                    sa[nj][3] = (c1 <= qq1) ? sa[nj][3] * k1 + slope2 * (float)(c1 - qq1) : NINF;
                    mloc0 = fmaxf(mloc0, fmaxf(sa[nj][0], sa[nj][1]));
                    mloc1 = fmaxf(mloc1, fmaxf(sa[nj][2], sa[nj][3]));
                }
            }
            mloc0 = fmaxf(mloc0, __shfl_xor_sync(0xffffffffu, mloc0, 1));
            mloc0 = fmaxf(mloc0, __shfl_xor_sync(0xffffffffu, mloc0, 2));
            mloc1 = fmaxf(mloc1, __shfl_xor_sync(0xffffffffu, mloc1, 1));
            mloc1 = fmaxf(mloc1, __shfl_xor_sync(0xffffffffu, mloc1, 2));
            float mn0 = fmaxf(m0, mloc0), mn1 = fmaxf(m1, mloc1);
            float corr0 = ex2(m0 - mn0), corr1 = ex2(m1 - mn1);
            m0 = mn0;
            m1 = mn1;
            float rs0 = 0.f, rs1 = 0.f;
            uint32_t ph[8][2];
#pragma unroll
            for (int nj = 0; nj < 8; nj++) {
                float p00 = ex2(sa[nj][0] - mn0);
                float p01 = ex2(sa[nj][1] - mn0);
                float p10 = ex2(sa[nj][2] - mn1);
                float p11 = ex2(sa[nj][3] - mn1);
                rs0 += p00 + p01;
                rs1 += p10 + p11;
                ph[nj][0] = cvt_f16x2(p00, p01);
                ph[nj][1] = cvt_f16x2(p10, p11);
            }
            rs0 += __shfl_xor_sync(0xffffffffu, rs0, 1);
            rs0 += __shfl_xor_sync(0xffffffffu, rs0, 2);
            rs1 += __shfl_xor_sync(0xffffffffu, rs1, 1);
            rs1 += __shfl_xor_sync(0xffffffffu, rs1, 2);
            l0 = l0 * corr0 + rs0;
            l1 = l1 * corr1 + rs1;
#pragma unroll
            for (int nd = 0; nd < 8; nd++) {
                oa[nd][0] *= corr0;
                oa[nd][1] *= corr0;
                oa[nd][2] *= corr1;
                oa[nd][3] *= corr1;
            }
            // --- O += P V ---
#pragma unroll
            for (int ks = 0; ks < 4; ks++) {
                uint32_t ah[4] = {ph[2 * ks][0], ph[2 * ks][1], ph[2 * ks + 1][0], ph[2 * ks + 1][1]};
                uint32_t vv[8][2];
#pragma unroll
                for (int nd = 0; nd < 8; nd++) {
                    uint32_t va = vbase + (nd * 8 + r) * AP + ks * 32 + tq * 4;
                    vv[nd][0] = lds32(va);
                    vv[nd][1] = lds32(va + 16);
                }
#pragma unroll
                for (int nd = 0; nd < 8; nd++) mma_f16(oa[nd], ah, vv[nd]);
            }
        }
        __syncthreads();
        if (t + 2 < nt) load_kv(t + 2); else CP_COMMIT();
    }

    // Epilogue: normalize, store single fp16
    const float inv0 = 1.f / l0, inv1 = 1.f / l1;
    const size_t row0 = (size_t)(b * 1024 + q0 + wrow + r) * 2048 + h * 64;
    const size_t row1 = row0 + (size_t)8 * 2048;
#pragma unroll
    for (int nd = 0; nd < 8; nd++) {
        int d0 = nd * 8 + 2 * tq;
        *(uint32_t*)&g_At2[row0 + d0] = cvt_f16x2(oa[nd][0] * inv0, oa[nd][1] * inv0);
        *(uint32_t*)&g_At2[row1 + d0] = cvt_f16x2(oa[nd][2] * inv1, oa[nd][3] * inv1);
    }
}

// ---------------------------------------------------------------------------
extern "C" void kernel_launch(void* const* d_in, const int* in_sizes, int n_in,
                              void* d_out, int out_size) {
    const float* inputs = (const float*)d_in[0];  // [4,1024,1024]
    const float* W_qkv  = (const float*)d_in[1];  // [1024,4096]
    const float* W_out  = (const float*)d_in[2];  // [2048,1024]
    float* out = (float*)d_out;                   // [4,1024,1024]

    cudaFuncSetAttribute(gemm_f16_kernel, cudaFuncAttributeMaxDynamicSharedMemorySize,
                         GSM1);
    cudaFuncSetAttribute(attn_tc_kernel, cudaFuncAttributeMaxDynamicSharedMemorySize,
                         ATT_SMEM);

    __half *A, *Wq, *A2, *Wo;
    cudaGetSymbolAddress((void**)&A, g_A);
    cudaGetSymbolAddress((void**)&Wq, g_Wqkv);
    cudaGetSymbolAddress((void**)&A2, g_At2);
    cudaGetSymbolAddress((void**)&Wo, g_Wout);

    // 1) merged input prep: A fp16 convert + both weight transposes
    prep_in_kernel<<<10240, 256>>>(inputs, W_qkv, W_out);

    // 2) QKV projection, fused epilogue -> g_Q/g_K fp16 + g_Vt (transposed V)
    gemm_f16_kernel<<<dim3(QKV_COLS / 128, ROWS / 128), 256, GSM1>>>(
        A, Wq, nullptr, QKV_COLS, HIDDEN, 1);

    // 3) tensor-core attention -> g_At2 fp16
    attn_tc_kernel<<<dim3(BATCH * 32, SEQL / 128), 256, ATT_SMEM>>>();

    // 4) Output projection -> out
    gemm_f16_kernel<<<dim3(HIDDEN / 128, ROWS / 128), 256, GSM1>>>(
        A2, Wo, out, HIDDEN, ATTN_COLS, 0);
}